// round 4
// baseline (speedup 1.0000x reference)
#include <cuda_runtime.h>
#include <stdint.h>

#define N_PART 32768
#define N_CENT 2048
// SC = -log2(e)/tau, tau = 1e-3
#define SC_CONST (-1442.6950408889634f)
#define NSPLIT 4
#define CSPL (N_CENT / NSPLIT)   // 512 centroids per split

__device__ float4 d_cabc[N_CENT];            // (A,B,C,0) per centroid, exp2-domain
__device__ float4 d_pA[N_PART];              // (x0, x1, w/Z, D)
__device__ float  d_acc[3 * N_CENT];         // accX | accY | accW
__device__ float  d_part[NSPLIT * N_PART];   // per-split partial Z
__device__ unsigned long long d_cand[4096];  // compacted top-k candidates
__device__ unsigned d_gcnt;
__device__ unsigned d_h16[65536];            // 16-bit histogram
__device__ unsigned d_T;                     // 32-bit threshold bits

__device__ __forceinline__ float fast_exp2(float x) {
    float r;
    asm("ex2.approx.ftz.f32 %0, %1;" : "=f"(r) : "f"(x));
    return r;
}

// ---------------------------------------------------------------------------
// K0: zero scratch (hist, counters, accumulators). Grid-wide.
// ---------------------------------------------------------------------------
__global__ void __launch_bounds__(512) k_zero() {
    const int t = blockIdx.x * 512 + threadIdx.x;
    for (int i = t; i < 65536; i += 64 * 512) d_h16[i] = 0u;
    if (t < 3 * N_CENT) d_acc[t] = 0.0f;
    if (t == 0) d_gcnt = 0u;
}

// ---------------------------------------------------------------------------
// K1: grid-wide histogram of top-16 float bits (w >= 0 -> bits monotone).
// ---------------------------------------------------------------------------
__global__ void __launch_bounds__(512) k_hist16(const float* __restrict__ w) {
    const int i = blockIdx.x * 512 + threadIdx.x;
    unsigned b = __float_as_uint(w[i]);
    atomicAdd(&d_h16[b >> 16], 1u);
}

// ---------------------------------------------------------------------------
// K2 (single block): locate the 16-bit bucket of the k-th largest, then two
// filtered 8-bit passes over the low bits -> exact 32-bit threshold T.
// ---------------------------------------------------------------------------
__global__ void __launch_bounds__(1024) k_finish(const float* __restrict__ w) {
    __shared__ unsigned part[1024];
    __shared__ unsigned hist[256];
    __shared__ unsigned s_prefix, s_k;
    const int tid = threadIdx.x;

    unsigned s = 0;
#pragma unroll 8
    for (int j = 0; j < 64; ++j) s += d_h16[tid * 64 + j];
    part[tid] = s;
    __syncthreads();

    if (tid == 0) {
        unsigned kk = N_CENT, cum = 0;
        int t = 1023;
        while (t > 0 && cum + part[t] < kk) { cum += part[t]; --t; }
        kk -= cum;
        unsigned cum2 = 0;
        int d = 63;
        while (d > 0 && cum2 + d_h16[t * 64 + d] < kk) { cum2 += d_h16[t * 64 + d]; --d; }
        s_prefix = (unsigned)(t * 64 + d);
        s_k = kk - cum2;
    }
    __syncthreads();

    unsigned prefix = s_prefix;   // 16-bit prefix
    unsigned kk = s_k;

    for (int pass = 0; pass < 2; ++pass) {
        const int shift = 8 - 8 * pass;
        if (tid < 256) hist[tid] = 0;
        __syncthreads();
        for (int i = tid; i < N_PART; i += 1024) {
            unsigned b = __float_as_uint(w[i]);
            if ((b >> (shift + 8)) == prefix)
                atomicAdd(&hist[(b >> shift) & 255u], 1u);
        }
        __syncthreads();
        if (tid == 0) {
            unsigned cum = 0;
            int d = 255;
            while (d > 0 && cum + hist[d] < kk) { cum += hist[d]; --d; }
            s_prefix = (prefix << 8) | (unsigned)d;
            s_k = kk - cum;
        }
        __syncthreads();
        prefix = s_prefix;
        kk = s_k;
        __syncthreads();
    }
    if (tid == 0) d_T = prefix;
}

// ---------------------------------------------------------------------------
// K3: grid-wide compaction of candidates with bits >= T.
// ---------------------------------------------------------------------------
__global__ void __launch_bounds__(512) k_compact(const float* __restrict__ w) {
    const int i = blockIdx.x * 512 + threadIdx.x;
    unsigned b = __float_as_uint(w[i]);
    if (b >= d_T) {
        unsigned p = atomicAdd(&d_gcnt, 1u);
        if (p < 4096u)
            d_cand[p] = ((unsigned long long)b << 32) | (unsigned)(~i);
    }
}

// ---------------------------------------------------------------------------
// K4: rank candidates by counting strictly-greater keys (keys unique).
// rank < 2048 -> emit centroid constants in exact jax.lax.top_k order.
// ---------------------------------------------------------------------------
__global__ void __launch_bounds__(512) k_rank(const float* __restrict__ x) {
    __shared__ unsigned long long keys[4096];
    const int tid = threadIdx.x;
    const unsigned C = min(d_gcnt, 4096u);

    for (int j = tid; j < (int)C; j += 512) keys[j] = d_cand[j];
    __syncthreads();

    const int lane = tid & 31;
    const int wslot = blockIdx.x * 16 + (tid >> 5);   // 256 warp slots

    for (int c = wslot; c < (int)C; c += 256) {
        const unsigned long long key = keys[c];
        int r = 0;
        for (int j = lane; j < (int)C; j += 32) r += (keys[j] > key);
        r = __reduce_add_sync(0xffffffffu, r);
        if (lane == 0 && r < N_CENT) {
            unsigned idx = ~((unsigned)(key & 0xFFFFFFFFull));
            float cx = x[2 * idx], cy = x[2 * idx + 1];
            float A = SC_CONST * (-2.0f * cx);
            float B = SC_CONST * (-2.0f * cy);
            float Cc = SC_CONST * (cx * cx + cy * cy);
            d_cabc[r] = make_float4(A, B, Cc, 0.0f);
        }
    }
}

// ---------------------------------------------------------------------------
// K5: per-particle partial Z over a 512-centroid split.
// u = A*x0 + B*x1 + C + D  with D = SC*||x||^2  ==> u = SC*d^2 in [-2886, 0]:
// no overflow; FTZ underflow only for negligible terms. No max shift needed.
// ---------------------------------------------------------------------------
__global__ void __launch_bounds__(128) k_pass2(const float* __restrict__ x) {
    __shared__ float4 sc[CSPL];   // 8 KB
    const int tid = threadIdx.x;
    const int split = blockIdx.y;
    for (int j = tid; j < CSPL; j += 128) sc[j] = d_cabc[split * CSPL + j];
    __syncthreads();

    const int n = blockIdx.x * 128 + tid;
    const float2 xn = ((const float2*)x)[n];
    const float x0 = xn.x, x1 = xn.y;
    const float D = SC_CONST * (x0 * x0 + x1 * x1);

    float z0 = 0.f, z1 = 0.f, z2 = 0.f, z3 = 0.f;
    for (int m = 0; m < CSPL; m += 4) {
        float4 c0 = sc[m + 0], c1 = sc[m + 1], c2 = sc[m + 2], c3 = sc[m + 3];
        z0 += fast_exp2(fmaf(c0.x, x0, fmaf(c0.y, x1, c0.z)) + D);
        z1 += fast_exp2(fmaf(c1.x, x0, fmaf(c1.y, x1, c1.z)) + D);
        z2 += fast_exp2(fmaf(c2.x, x0, fmaf(c2.y, x1, c2.z)) + D);
        z3 += fast_exp2(fmaf(c3.x, x0, fmaf(c3.y, x1, c3.z)) + D);
    }
    d_part[split * N_PART + n] = (z0 + z1) + (z2 + z3);
}

// ---------------------------------------------------------------------------
// K6: combine split partials (exact: Z = sum Z_i) -> particle record.
// ---------------------------------------------------------------------------
__global__ void __launch_bounds__(256) k_combine(const float* __restrict__ x,
                                                const float* __restrict__ w) {
    const int n = blockIdx.x * 256 + threadIdx.x;
    const float Z = d_part[0 * N_PART + n] + d_part[1 * N_PART + n]
                  + d_part[2 * N_PART + n] + d_part[3 * N_PART + n];
    const float2 xn = ((const float2*)x)[n];
    const float pw = w[n] / Z;
    const float D = SC_CONST * (xn.x * xn.x + xn.y * xn.y);
    d_pA[n] = make_float4(xn.x, xn.y, pw, D);
}

// ---------------------------------------------------------------------------
// K7: gather per centroid, register accumulators.
// 512 blocks x 256 threads: blockIdx = (chunk<<3)|group; thread = centroid.
// Streams 512-particle chunks through smem (LDS broadcast).
// ---------------------------------------------------------------------------
__global__ void __launch_bounds__(256) k_pass3() {
    __shared__ float4 sp[512];   // 8 KB
    const int tid = threadIdx.x;
    const int g = blockIdx.x & 7;
    const int chunk = blockIdx.x >> 3;
    const int m = g * 256 + tid;
    const float4 cc = d_cabc[m];
    const int base = chunk * 512;

    for (int j = tid; j < 512; j += 256) sp[j] = d_pA[base + j];
    __syncthreads();

    float a0 = 0.f, a1 = 0.f, a2 = 0.f;
#pragma unroll 8
    for (int j = 0; j < 512; ++j) {
        float4 p = sp[j];
        float u = fmaf(cc.x, p.x, fmaf(cc.y, p.y, cc.z)) + p.w;  // = SC*d^2 <= 0
        float t = fast_exp2(u) * p.z;                            // att_unnorm * w / Z
        a0 = fmaf(t, p.x, a0);
        a1 = fmaf(t, p.y, a1);
        a2 += t;
    }

    atomicAdd(&d_acc[m], a0);
    atomicAdd(&d_acc[N_CENT + m], a1);
    atomicAdd(&d_acc[2 * N_CENT + m], a2);
}

// ---------------------------------------------------------------------------
// K8: finalize y = num/den, v = den.
// ---------------------------------------------------------------------------
__global__ void __launch_bounds__(256) k_final(float* __restrict__ out) {
    const int m = blockIdx.x * 256 + threadIdx.x;
    if (m < N_CENT) {
        float nx = d_acc[m];
        float ny = d_acc[N_CENT + m];
        float den = d_acc[2 * N_CENT + m];
        out[2 * m + 0] = nx / den;
        out[2 * m + 1] = ny / den;
        out[2 * N_CENT + m] = den;
    }
}

extern "C" void kernel_launch(void* const* d_in, const int* in_sizes, int n_in,
                              void* d_out, int out_size) {
    const float* x = (const float*)d_in[0];   // [32768, 2]
    const float* w = (const float*)d_in[1];   // [32768]
    float* out = (float*)d_out;               // 6144 floats: y (4096) then v (2048)

    k_zero<<<64, 512>>>();
    k_hist16<<<64, 512>>>(w);
    k_finish<<<1, 1024>>>(w);
    k_compact<<<64, 512>>>(w);
    k_rank<<<16, 512>>>(x);
    k_pass2<<<dim3(256, NSPLIT), 128>>>(x);
    k_combine<<<128, 256>>>(x, w);
    k_pass3<<<512, 256>>>();
    k_final<<<8, 256>>>(out);
}

// round 5
// speedup vs baseline: 1.9532x; 1.9532x over previous
#include <cuda_runtime.h>
#include <stdint.h>

#define N_PART 32768
#define N_CENT 2048
// SC = -log2(e)/tau, tau = 1e-3
#define SC_CONST (-1442.6950408889634f)
#define G 148          // grid blocks (<= SM count -> all co-resident)
#define B 512          // threads per block
#define NBINS 8192     // histogram bins = top 13 float bits

__device__ float4 d_cabc[N_CENT];            // (A,B,C,0) per centroid
__device__ float4 d_pA[N_PART];              // (x0, x1, D, pw)
__device__ float2 d_pB[N_PART];              // (pw*x0, pw*x1)
__device__ float  d_acc[3 * N_CENT];         // accX | accY | accW
__device__ unsigned long long d_cand[4096];
__device__ unsigned d_gcnt;
__device__ unsigned d_hist[NBINS];
__device__ unsigned d_bar[8];                // monotonic barrier counters

union SmU {
    unsigned long long keys[4096];   // 32 KB (rank phase)
    float4 cabc[N_CENT];             // 32 KB (Z + gather phases)
    unsigned scan[B];                // scan phase
};

__device__ __forceinline__ float fast_exp2(float x) {
    float r;
    asm("ex2.approx.ftz.f32 %0, %1;" : "=f"(r) : "f"(x));
    return r;
}

// Software grid barrier. Monotonic counter: each run adds exactly G arrivals,
// so "round my ticket up to the next multiple of G" is the release target —
// no reset needed across graph replays.
__device__ __forceinline__ void gbar(int id) {
    __syncthreads();
    if (threadIdx.x == 0) {
        __threadfence();                                   // release
        unsigned my = atomicAdd(&d_bar[id], 1u) + 1u;
        unsigned tgt = ((my + G - 1u) / G) * G;
        while (*((volatile unsigned*)&d_bar[id]) < tgt) { }
        __threadfence();                                   // acquire
    }
    __syncthreads();
}

__global__ void __launch_bounds__(B) k_all(const float* __restrict__ x,
                                           const float* __restrict__ w,
                                           float* __restrict__ out) {
    __shared__ SmU sm;
    __shared__ float zpart[8][2][32];
    __shared__ float4 pbuf[128];
    __shared__ float2 pbuf2[128];
    __shared__ unsigned s_tbin;

    const int tid = threadIdx.x;
    const int bid = blockIdx.x;
    const int gid = bid * B + tid;

    // ---- P0: zero scratch ----
    if (gid < NBINS) d_hist[gid] = 0u;
    else if (gid < NBINS + 3 * N_CENT) d_acc[gid - NBINS] = 0.0f;
    else if (gid == NBINS + 3 * N_CENT) d_gcnt = 0u;
    gbar(0);

    // ---- P1: histogram of top-13 float bits (w >= 0 -> bits monotone) ----
    unsigned wb = 0;
    if (gid < N_PART) {
        wb = __float_as_uint(w[gid]);
        atomicAdd(&d_hist[wb >> 19], 1u);
    }
    gbar(1);

    // ---- P2: redundant per-block suffix scan -> threshold bin ----
    {
        unsigned s = 0;
#pragma unroll
        for (int j = 0; j < NBINS / B; ++j) s += __ldcg(&d_hist[tid * (NBINS / B) + j]);
        sm.scan[tid] = s;
        __syncthreads();
        for (int off = 1; off < B; off <<= 1) {
            unsigned v = sm.scan[tid] + ((tid + off < B) ? sm.scan[tid + off] : 0u);
            __syncthreads();
            sm.scan[tid] = v;
            __syncthreads();
        }
        // unique crossing: suffix[tid] >= K and suffix[tid+1] < K
        if (sm.scan[tid] >= N_CENT && (tid == B - 1 || sm.scan[tid + 1] < N_CENT)) {
            unsigned cum = (tid + 1 < B) ? sm.scan[tid + 1] : 0u;
            unsigned tb = (unsigned)(tid * (NBINS / B));
            for (int bin = tid * (NBINS / B) + NBINS / B - 1; bin >= tid * (NBINS / B); --bin) {
                cum += __ldcg(&d_hist[bin]);
                if (cum >= N_CENT) { tb = (unsigned)bin; break; }
            }
            s_tbin = tb;
        }
        __syncthreads();
    }
    const unsigned T = s_tbin << 19;

    // ---- P3: compact candidates (bits >= T) ----
    if (gid < N_PART && wb >= T) {
        unsigned p = atomicAdd(&d_gcnt, 1u);
        if (p < 4096u)
            d_cand[p] = ((unsigned long long)wb << 32) | (unsigned)(~gid);
    }
    gbar(2);

    // ---- P4: exact rank (desc weight, ties -> lower index), emit centroids ----
    {
        const unsigned C = min(__ldcg(&d_gcnt), 4096u);
        for (int j = tid; j < (int)C; j += B) sm.keys[j] = __ldcg(&d_cand[j]);
        __syncthreads();
        const int lane = tid & 31;
        const int ws = bid * (B / 32) + (tid >> 5);
        for (int c = ws; c < (int)C; c += G * (B / 32)) {
            const unsigned long long key = sm.keys[c];
            int r = 0;
            for (int j = lane; j < (int)C; j += 32) r += (sm.keys[j] > key);
            r = __reduce_add_sync(0xffffffffu, r);
            if (lane == 0 && r < N_CENT) {
                unsigned idx = ~((unsigned)(key & 0xFFFFFFFFull));
                float cx = x[2 * idx], cy = x[2 * idx + 1];
                d_cabc[r] = make_float4(SC_CONST * (-2.0f * cx),
                                        SC_CONST * (-2.0f * cy),
                                        SC_CONST * (cx * cx + cy * cy), 0.0f);
            }
        }
    }
    gbar(3);

    // ---- P5: per-particle Z. u = A*x0+B*x1+C+D = SC*d^2 in [-2886, 0]. ----
    // 2 warps per 32-particle group (centroid halves), combined in smem.
    for (int j = tid; j < N_CENT; j += B)
        sm.cabc[j] = __ldcg(&d_cabc[j]);
    __syncthreads();
    {
        const int wid = tid >> 5, lane = tid & 31;
        const int half = wid & 1, gslot = wid >> 1;     // gslot 0..7
        const int g = bid + gslot * G;                  // particle group
        float x0 = 0.f, x1 = 0.f, D = 0.f;
        const bool act = (g < N_PART / 32);
        if (act) {
            const int p = g * 32 + lane;
            float2 xn = ((const float2*)x)[p];
            x0 = xn.x; x1 = xn.y;
            D = SC_CONST * (x0 * x0 + x1 * x1);
            const int base = half * (N_CENT / 2);
            float z0 = 0.f, z1 = 0.f, z2 = 0.f, z3 = 0.f;
            for (int m = 0; m < N_CENT / 2; m += 4) {
                float4 c0 = sm.cabc[base + m + 0], c1 = sm.cabc[base + m + 1];
                float4 c2 = sm.cabc[base + m + 2], c3 = sm.cabc[base + m + 3];
                z0 += fast_exp2(fmaf(c0.x, x0, fmaf(c0.y, x1, c0.z)) + D);
                z1 += fast_exp2(fmaf(c1.x, x0, fmaf(c1.y, x1, c1.z)) + D);
                z2 += fast_exp2(fmaf(c2.x, x0, fmaf(c2.y, x1, c2.z)) + D);
                z3 += fast_exp2(fmaf(c3.x, x0, fmaf(c3.y, x1, c3.z)) + D);
            }
            zpart[gslot][half][lane] = (z0 + z1) + (z2 + z3);
        }
        __syncthreads();
        if (act && half == 0) {
            const int p = g * 32 + lane;
            float Z = zpart[gslot][0][lane] + zpart[gslot][1][lane];
            float pw = w[p] / Z;
            d_pA[p] = make_float4(x0, x1, D, pw);
            d_pB[p] = make_float2(pw * x0, pw * x1);
        }
    }
    gbar(4);

    // ---- P6: gather. Each thread owns 4 centroids; stream 128-particle chunks ----
    {
        float cA[4], cB[4], cC[4];
        float ax[4] = {0, 0, 0, 0}, ay[4] = {0, 0, 0, 0}, aw[4] = {0, 0, 0, 0};
#pragma unroll
        for (int k = 0; k < 4; ++k) {
            float4 c = sm.cabc[tid + B * k];
            cA[k] = c.x; cB[k] = c.y; cC[k] = c.z;
        }
        for (int ch = bid; ch < N_PART / 128; ch += G) {
            __syncthreads();
            if (tid < 128) {
                pbuf[tid]  = __ldcg(&d_pA[ch * 128 + tid]);
                pbuf2[tid] = __ldcg(&d_pB[ch * 128 + tid]);
            }
            __syncthreads();
#pragma unroll 4
            for (int j = 0; j < 128; ++j) {
                float4 p = pbuf[j];
                float2 q = pbuf2[j];
#pragma unroll
                for (int k = 0; k < 4; ++k) {
                    float u = fmaf(cA[k], p.x, fmaf(cB[k], p.y, cC[k])) + p.z;
                    float e = fast_exp2(u);
                    ax[k] = fmaf(e, q.x, ax[k]);
                    ay[k] = fmaf(e, q.y, ay[k]);
                    aw[k] = fmaf(e, p.w, aw[k]);
                }
            }
        }
#pragma unroll
        for (int k = 0; k < 4; ++k) {
            const int m = tid + B * k;
            atomicAdd(&d_acc[m], ax[k]);
            atomicAdd(&d_acc[N_CENT + m], ay[k]);
            atomicAdd(&d_acc[2 * N_CENT + m], aw[k]);
        }
    }
    gbar(5);

    // ---- P7: finalize ----
    if (gid < N_CENT) {
        float nx = __ldcg(&d_acc[gid]);
        float ny = __ldcg(&d_acc[N_CENT + gid]);
        float dn = __ldcg(&d_acc[2 * N_CENT + gid]);
        out[2 * gid + 0] = nx / dn;
        out[2 * gid + 1] = ny / dn;
        out[2 * N_CENT + gid] = dn;
    }
}

extern "C" void kernel_launch(void* const* d_in, const int* in_sizes, int n_in,
                              void* d_out, int out_size) {
    const float* x = (const float*)d_in[0];   // [32768, 2]
    const float* w = (const float*)d_in[1];   // [32768]
    float* out = (float*)d_out;               // 6144 floats: y (4096) then v (2048)

    k_all<<<G, B>>>(x, w, out);
}

// round 6
// speedup vs baseline: 1.9601x; 1.0035x over previous
#include <cuda_runtime.h>
#include <stdint.h>

#define N_PART 32768
#define N_CENT 2048
// SC = -log2(e)/tau, tau = 1e-3
#define SC_CONST (-1442.6950408889634f)
#define G 148           // blocks == SMs -> co-resident, grid barrier safe
#define B 1024          // threads per block (32 warps/SM)
#define NBINS 8192      // top-13 float bits
#define PPB 222         // ceil(N_PART / G) particles per block in Z pass
#define NCHUNK 512      // 64-particle chunks in gather pass

__device__ float4 d_cabc[N_CENT];            // (A,B,C,0) per centroid
__device__ float  d_soa[6 * N_PART];         // x0 | x1 | D | pw | pw*x0 | pw*x1
__device__ float  d_acc[3 * N_CENT];         // accX | accY | accW
__device__ unsigned long long d_cand[4096];
__device__ unsigned d_gcnt, d_tick;
__device__ unsigned d_hist[NBINS];
__device__ unsigned d_bar[8];                // monotonic barrier counters

union SmU {
    unsigned long long keys[4096];   // 32 KB (rank phase)
    float4 cabc[N_CENT];             // 32 KB (Z + gather phases)
    unsigned scan[B];                // scan phase
};

typedef unsigned long long u64;

__device__ __forceinline__ float fast_exp2(float x) {
    float r;
    asm("ex2.approx.ftz.f32 %0, %1;" : "=f"(r) : "f"(x));
    return r;
}
__device__ __forceinline__ u64 pk(float lo, float hi) {
    u64 r; asm("mov.b64 %0, {%1, %2};" : "=l"(r) : "f"(lo), "f"(hi)); return r;
}
__device__ __forceinline__ void upk(float& lo, float& hi, u64 v) {
    asm("mov.b64 {%0, %1}, %2;" : "=f"(lo), "=f"(hi) : "l"(v));
}
__device__ __forceinline__ u64 fma2(u64 a, u64 b, u64 c) {
    u64 r; asm("fma.rn.f32x2 %0, %1, %2, %3;" : "=l"(r) : "l"(a), "l"(b), "l"(c)); return r;
}
__device__ __forceinline__ u64 add2(u64 a, u64 b) {
    u64 r; asm("add.rn.f32x2 %0, %1, %2;" : "=l"(r) : "l"(a), "l"(b)); return r;
}

// Software grid barrier; monotonic counter, graph-replay safe.
__device__ __forceinline__ void gbar(int id) {
    __syncthreads();
    if (threadIdx.x == 0) {
        __threadfence();
        unsigned my = atomicAdd(&d_bar[id], 1u) + 1u;
        unsigned tgt = ((my + G - 1u) / G) * G;
        while (*((volatile unsigned*)&d_bar[id]) < tgt) { }
        __threadfence();
    }
    __syncthreads();
}

__global__ void __launch_bounds__(B, 1) k_all(const float* __restrict__ x,
                                              const float* __restrict__ w,
                                              float* __restrict__ out) {
    __shared__ SmU sm;
    __shared__ float zpart[256][4];
    __shared__ float2 s_buf[192];        // 6 arrays x 32 pairs
    __shared__ unsigned s_tbin, s_chunk;

    const int tid = threadIdx.x;
    const int bid = blockIdx.x;
    const int gid = bid * B + tid;

    // ---- P0: zero scratch ----
    if (gid < NBINS) d_hist[gid] = 0u;
    else if (gid < NBINS + 3 * N_CENT) d_acc[gid - NBINS] = 0.0f;
    else if (gid == NBINS + 3 * N_CENT) { d_gcnt = 0u; d_tick = 0u; }
    gbar(0);

    // ---- P1: histogram of top-13 float bits (w >= 0 -> bits monotone) ----
    unsigned wb = 0;
    if (gid < N_PART) {
        wb = __float_as_uint(w[gid]);
        atomicAdd(&d_hist[wb >> 19], 1u);
    }
    gbar(1);

    // ---- P2: redundant per-block suffix scan -> threshold bin ----
    {
        unsigned s = 0;
#pragma unroll
        for (int j = 0; j < NBINS / B; ++j) s += __ldcg(&d_hist[tid * (NBINS / B) + j]);
        sm.scan[tid] = s;
        __syncthreads();
        for (int off = 1; off < B; off <<= 1) {
            unsigned v = sm.scan[tid] + ((tid + off < B) ? sm.scan[tid + off] : 0u);
            __syncthreads();
            sm.scan[tid] = v;
            __syncthreads();
        }
        if (sm.scan[tid] >= N_CENT && (tid == B - 1 || sm.scan[tid + 1] < N_CENT)) {
            unsigned cum = (tid + 1 < B) ? sm.scan[tid + 1] : 0u;
            unsigned tb = (unsigned)(tid * (NBINS / B));
            for (int bin = tid * (NBINS / B) + NBINS / B - 1; bin >= tid * (NBINS / B); --bin) {
                cum += __ldcg(&d_hist[bin]);
                if (cum >= N_CENT) { tb = (unsigned)bin; break; }
            }
            s_tbin = tb;
        }
        __syncthreads();
    }
    const unsigned T = s_tbin << 19;

    // ---- P3: compact candidates (bits >= T) ----
    if (gid < N_PART && wb >= T) {
        unsigned p = atomicAdd(&d_gcnt, 1u);
        if (p < 4096u)
            d_cand[p] = ((unsigned long long)wb << 32) | (unsigned)(~gid);
    }
    gbar(2);

    // ---- P4: exact rank (desc weight, ties -> lower index), emit centroids ----
    {
        const unsigned C = min(__ldcg(&d_gcnt), 4096u);
        for (int j = tid; j < (int)C; j += B) sm.keys[j] = __ldcg(&d_cand[j]);
        __syncthreads();
        const int lane = tid & 31;
        const int ws = bid * (B / 32) + (tid >> 5);
        for (int c = ws; c < (int)C; c += G * (B / 32)) {
            const unsigned long long key = sm.keys[c];
            int r = 0;
            for (int j = lane; j < (int)C; j += 32) r += (sm.keys[j] > key);
            r = __reduce_add_sync(0xffffffffu, r);
            if (lane == 0 && r < N_CENT) {
                unsigned idx = ~((unsigned)(key & 0xFFFFFFFFull));
                float cx = x[2 * idx], cy = x[2 * idx + 1];
                d_cabc[r] = make_float4(SC_CONST * (-2.0f * cx),
                                        SC_CONST * (-2.0f * cy),
                                        SC_CONST * (cx * cx + cy * cy), 0.0f);
            }
        }
    }
    gbar(3);

    // ---- P5: per-particle Z. Each thread: one particle, one centroid quarter.
    // u = A*x0 + B*x1 + C + D = SC*d^2 in [-2886, 0]: no overflow, safe FTZ.
    for (int j = tid; j < N_CENT; j += B) sm.cabc[j] = __ldcg(&d_cabc[j]);
    __syncthreads();
    {
        const int local = tid & 255;
        const int q = tid >> 8;                    // centroid quarter 0..3
        const int base = bid * PPB;
        const int cnt = min(PPB, N_PART - base);
        const bool act = (local < cnt);
        float x0 = 0.f, x1 = 0.f;
        if (act) {
            const int p = base + local;
            float2 xn = ((const float2*)x)[p];
            x0 = xn.x; x1 = xn.y;
            const float D = SC_CONST * (x0 * x0 + x1 * x1);
            const int mb = q * 512;
            float z0 = 0.f, z1 = 0.f, z2 = 0.f, z3 = 0.f;
            for (int m = 0; m < 512; m += 4) {
                float4 c0 = sm.cabc[mb + m + 0], c1 = sm.cabc[mb + m + 1];
                float4 c2 = sm.cabc[mb + m + 2], c3 = sm.cabc[mb + m + 3];
                z0 += fast_exp2(fmaf(c0.x, x0, fmaf(c0.y, x1, c0.z)) + D);
                z1 += fast_exp2(fmaf(c1.x, x0, fmaf(c1.y, x1, c1.z)) + D);
                z2 += fast_exp2(fmaf(c2.x, x0, fmaf(c2.y, x1, c2.z)) + D);
                z3 += fast_exp2(fmaf(c3.x, x0, fmaf(c3.y, x1, c3.z)) + D);
            }
            zpart[local][q] = (z0 + z1) + (z2 + z3);
        }
        __syncthreads();
        if (act && q == 0) {
            const int p = base + local;
            const float Z = zpart[local][0] + zpart[local][1]
                          + zpart[local][2] + zpart[local][3];
            const float pw = w[p] / Z;
            const float D = SC_CONST * (x0 * x0 + x1 * x1);
            d_soa[0 * N_PART + p] = x0;
            d_soa[1 * N_PART + p] = x1;
            d_soa[2 * N_PART + p] = D;
            d_soa[3 * N_PART + p] = pw;
            d_soa[4 * N_PART + p] = pw * x0;
            d_soa[5 * N_PART + p] = pw * x1;
        }
    }
    gbar(4);

    // ---- P6: gather, f32x2-packed over particle pairs. 2 centroids/thread. ----
    {
        const int m0 = 2 * tid, m1 = 2 * tid + 1;
        float4 c0 = sm.cabc[m0], c1 = sm.cabc[m1];
        const u64 A0 = pk(c0.x, c0.x), B0 = pk(c0.y, c0.y), C0 = pk(c0.z, c0.z);
        const u64 A1 = pk(c1.x, c1.x), B1 = pk(c1.y, c1.y), C1 = pk(c1.z, c1.z);
        u64 ax0 = 0, ay0 = 0, aw0 = 0, ax1 = 0, ay1 = 0, aw1 = 0;

        for (;;) {
            if (tid == 0) s_chunk = atomicAdd(&d_tick, 1u);
            __syncthreads();
            const unsigned c = s_chunk;
            if (c >= NCHUNK) break;
            if (tid < 192) {
                const int a = tid >> 5, e = tid & 31;
                s_buf[a * 32 + e] =
                    __ldcg(&((const float2*)(d_soa + a * N_PART))[c * 32 + e]);
            }
            __syncthreads();
            const u64* sb = (const u64*)s_buf;
#pragma unroll 2
            for (int j = 0; j < 32; ++j) {
                const u64 px2 = sb[j],        py2 = sb[32 + j],  pD2 = sb[64 + j];
                const u64 pw2 = sb[96 + j],   qx2 = sb[128 + j], qy2 = sb[160 + j];
                {
                    u64 u2 = add2(fma2(A0, px2, fma2(B0, py2, C0)), pD2);
                    float ua, ub; upk(ua, ub, u2);
                    u64 e2 = pk(fast_exp2(ua), fast_exp2(ub));
                    ax0 = fma2(e2, qx2, ax0);
                    ay0 = fma2(e2, qy2, ay0);
                    aw0 = fma2(e2, pw2, aw0);
                }
                {
                    u64 u2 = add2(fma2(A1, px2, fma2(B1, py2, C1)), pD2);
                    float ua, ub; upk(ua, ub, u2);
                    u64 e2 = pk(fast_exp2(ua), fast_exp2(ub));
                    ax1 = fma2(e2, qx2, ax1);
                    ay1 = fma2(e2, qy2, ay1);
                    aw1 = fma2(e2, pw2, aw1);
                }
            }
            __syncthreads();
        }
        float la, lb;
        upk(la, lb, ax0); atomicAdd(&d_acc[m0], la + lb);
        upk(la, lb, ay0); atomicAdd(&d_acc[N_CENT + m0], la + lb);
        upk(la, lb, aw0); atomicAdd(&d_acc[2 * N_CENT + m0], la + lb);
        upk(la, lb, ax1); atomicAdd(&d_acc[m1], la + lb);
        upk(la, lb, ay1); atomicAdd(&d_acc[N_CENT + m1], la + lb);
        upk(la, lb, aw1); atomicAdd(&d_acc[2 * N_CENT + m1], la + lb);
    }
    gbar(5);

    // ---- P7: finalize ----
    if (gid < N_CENT) {
        float nx = __ldcg(&d_acc[gid]);
        float ny = __ldcg(&d_acc[N_CENT + gid]);
        float dn = __ldcg(&d_acc[2 * N_CENT + gid]);
        out[2 * gid + 0] = nx / dn;
        out[2 * gid + 1] = ny / dn;
        out[2 * N_CENT + gid] = dn;
    }
}

extern "C" void kernel_launch(void* const* d_in, const int* in_sizes, int n_in,
                              void* d_out, int out_size) {
    const float* x = (const float*)d_in[0];   // [32768, 2]
    const float* w = (const float*)d_in[1];   // [32768]
    float* out = (float*)d_out;               // 6144 floats: y (4096) then v (2048)

    k_all<<<G, B>>>(x, w, out);
}

// round 7
// speedup vs baseline: 2.1425x; 1.0931x over previous
#include <cuda_runtime.h>
#include <stdint.h>

#define N_PART 32768
#define N_CENT 2048
// SC = -log2(e)/tau, tau = 1e-3
#define SC_CONST (-1442.6950408889634f)
#define G 148           // blocks == SMs -> co-resident, grid barrier safe
#define B 1024          // threads per block (32 warps/SM)
#define NBINS 8192      // top-13 float bits
#define PPB 222         // ceil(N_PART / G) particles per block in Z pass
#define NCHUNK 512      // 64-particle chunks in gather pass

__device__ float4 d_cabc[N_CENT];            // (A,B,C,0) per centroid
__device__ float  d_soa[6 * N_PART];         // x0 | x1 | D | pw | pw*x0 | pw*x1
__device__ float  d_acc[3 * N_CENT];         // accX | accY | accW
__device__ unsigned long long d_cand[4096];
__device__ unsigned d_gcnt, d_tick;
__device__ unsigned d_hist[NBINS];
__device__ unsigned d_bar[8];                // monotonic barrier counters

typedef unsigned long long u64;

// 32 KB union: rank keys  OR  packed centroid constants (pairs)
union SmU {
    unsigned long long keys[4096];           // 32 KB (rank phase)
    struct {
        u64 A2[N_CENT / 2];                  // (A_2j, A_2j+1)
        u64 B2[N_CENT / 2];
        u64 C2[N_CENT / 2];
        unsigned scan[B];                    // fits in the 4th KB-block
    } p;
};

__device__ __forceinline__ float fast_exp2(float x) {
    float r;
    asm("ex2.approx.ftz.f32 %0, %1;" : "=f"(r) : "f"(x));
    return r;
}
__device__ __forceinline__ u64 pk(float lo, float hi) {
    u64 r; asm("mov.b64 %0, {%1, %2};" : "=l"(r) : "f"(lo), "f"(hi)); return r;
}
__device__ __forceinline__ void upk(float& lo, float& hi, u64 v) {
    asm("mov.b64 {%0, %1}, %2;" : "=f"(lo), "=f"(hi) : "l"(v));
}
__device__ __forceinline__ u64 fma2(u64 a, u64 b, u64 c) {
    u64 r; asm("fma.rn.f32x2 %0, %1, %2, %3;" : "=l"(r) : "l"(a), "l"(b), "l"(c)); return r;
}
__device__ __forceinline__ u64 add2(u64 a, u64 b) {
    u64 r; asm("add.rn.f32x2 %0, %1, %2;" : "=l"(r) : "l"(a), "l"(b)); return r;
}

// Software grid barrier; monotonic counter, graph-replay safe.
__device__ __forceinline__ void gbar(int id) {
    __syncthreads();
    if (threadIdx.x == 0) {
        __threadfence();
        unsigned my = atomicAdd(&d_bar[id], 1u) + 1u;
        unsigned tgt = ((my + G - 1u) / G) * G;
        while (*((volatile unsigned*)&d_bar[id]) < tgt) { }
        __threadfence();
    }
    __syncthreads();
}

__global__ void __launch_bounds__(B, 1) k_all(const float* __restrict__ x,
                                              const float* __restrict__ w,
                                              float* __restrict__ out) {
    __shared__ SmU sm;
    __shared__ float zpart[256][4];
    __shared__ float2 s_buf[192];        // 6 arrays x 32 pairs
    __shared__ unsigned s_tbin, s_chunk;

    const int tid = threadIdx.x;
    const int bid = blockIdx.x;
    const int gid = bid * B + tid;

    // ---- P1: histogram of top-13 float bits; also zero d_acc (first atomic
    // touch of d_acc is after gbar(3), so any pre-P6 zero is safe).
    // d_hist/d_gcnt/d_tick are zeroed by the PREVIOUS run's tail (P7); the
    // very first run is covered by static zero-init.
    unsigned wb = 0;
    if (gid < N_PART) {
        wb = __float_as_uint(w[gid]);
        atomicAdd(&d_hist[wb >> 19], 1u);
    }
    if (gid < 3 * N_CENT) d_acc[gid] = 0.0f;
    gbar(0);

    // ---- P2: redundant per-block suffix scan -> threshold bin ----
    {
        unsigned s = 0;
#pragma unroll
        for (int j = 0; j < NBINS / B; ++j) s += __ldcg(&d_hist[tid * (NBINS / B) + j]);
        sm.p.scan[tid] = s;
        __syncthreads();
        for (int off = 1; off < B; off <<= 1) {
            unsigned v = sm.p.scan[tid] + ((tid + off < B) ? sm.p.scan[tid + off] : 0u);
            __syncthreads();
            sm.p.scan[tid] = v;
            __syncthreads();
        }
        if (sm.p.scan[tid] >= N_CENT && (tid == B - 1 || sm.p.scan[tid + 1] < N_CENT)) {
            unsigned cum = (tid + 1 < B) ? sm.p.scan[tid + 1] : 0u;
            unsigned tb = (unsigned)(tid * (NBINS / B));
            for (int bin = tid * (NBINS / B) + NBINS / B - 1; bin >= tid * (NBINS / B); --bin) {
                cum += __ldcg(&d_hist[bin]);
                if (cum >= N_CENT) { tb = (unsigned)bin; break; }
            }
            s_tbin = tb;
        }
        __syncthreads();
    }
    const unsigned T = s_tbin << 19;

    // ---- P3: compact candidates (bits >= T) ----
    if (gid < N_PART && wb >= T) {
        unsigned p = atomicAdd(&d_gcnt, 1u);
        if (p < 4096u)
            d_cand[p] = ((unsigned long long)wb << 32) | (unsigned)(~gid);
    }
    gbar(1);

    // ---- P4: exact rank (desc weight, ties -> lower index), emit centroids ----
    {
        const unsigned C = min(__ldcg(&d_gcnt), 4096u);
        for (int j = tid; j < (int)C; j += B) sm.keys[j] = __ldcg(&d_cand[j]);
        __syncthreads();
        const int lane = tid & 31;
        const int ws = bid * (B / 32) + (tid >> 5);
        for (int c = ws; c < (int)C; c += G * (B / 32)) {
            const unsigned long long key = sm.keys[c];
            int r = 0;
            for (int j = lane; j < (int)C; j += 32) r += (sm.keys[j] > key);
            r = __reduce_add_sync(0xffffffffu, r);
            if (lane == 0 && r < N_CENT) {
                unsigned idx = ~((unsigned)(key & 0xFFFFFFFFull));
                float cx = x[2 * idx], cy = x[2 * idx + 1];
                d_cabc[r] = make_float4(SC_CONST * (-2.0f * cx),
                                        SC_CONST * (-2.0f * cy),
                                        SC_CONST * (cx * cx + cy * cy), 0.0f);
            }
        }
    }
    gbar(2);

    // ---- stage packed centroid constants into smem (used by P5 and P6) ----
    for (int j = tid; j < N_CENT / 2; j += B) {
        float4 ca = __ldcg(&d_cabc[2 * j]);
        float4 cb = __ldcg(&d_cabc[2 * j + 1]);
        sm.p.A2[j] = pk(ca.x, cb.x);
        sm.p.B2[j] = pk(ca.y, cb.y);
        sm.p.C2[j] = pk(ca.z, cb.z);
    }
    __syncthreads();

    // ---- P5: per-particle Z, f32x2 over centroid pairs.
    // u = A*x0 + B*x1 + C + D = SC*d^2 in [-2886, 0]: no overflow, safe FTZ.
    // Each thread: one particle, one centroid quarter (256 pairs).
    {
        const int local = tid & 255;
        const int q = tid >> 8;                    // centroid quarter 0..3
        const int base = bid * PPB;
        const int cnt = min(PPB, N_PART - base);
        const bool act = (local < cnt);
        float x0 = 0.f, x1 = 0.f;
        if (act) {
            const int p = base + local;
            float2 xn = ((const float2*)x)[p];
            x0 = xn.x; x1 = xn.y;
            const float D = SC_CONST * (x0 * x0 + x1 * x1);
            const u64 xx0 = pk(x0, x0), xx1 = pk(x1, x1), DD = pk(D, D);
            const int pb = q * 256;                // pair base
            u64 zacc0 = 0, zacc1 = 0;
#pragma unroll 4
            for (int i = 0; i < 256; i += 2) {
                u64 u2a = fma2(sm.p.A2[pb + i], xx0,
                         fma2(sm.p.B2[pb + i], xx1, add2(sm.p.C2[pb + i], DD)));
                u64 u2b = fma2(sm.p.A2[pb + i + 1], xx0,
                         fma2(sm.p.B2[pb + i + 1], xx1, add2(sm.p.C2[pb + i + 1], DD)));
                float ua, ub, uc, ud;
                upk(ua, ub, u2a);
                upk(uc, ud, u2b);
                zacc0 = add2(zacc0, pk(fast_exp2(ua), fast_exp2(ub)));
                zacc1 = add2(zacc1, pk(fast_exp2(uc), fast_exp2(ud)));
            }
            float za, zb, zc, zd;
            upk(za, zb, zacc0);
            upk(zc, zd, zacc1);
            zpart[local][q] = (za + zb) + (zc + zd);
        }
        __syncthreads();
        if (act && q == 0) {
            const int p = base + local;
            const float Z = zpart[local][0] + zpart[local][1]
                          + zpart[local][2] + zpart[local][3];
            const float pw = w[p] / Z;
            const float D = SC_CONST * (x0 * x0 + x1 * x1);
            d_soa[0 * N_PART + p] = x0;
            d_soa[1 * N_PART + p] = x1;
            d_soa[2 * N_PART + p] = D;
            d_soa[3 * N_PART + p] = pw;
            d_soa[4 * N_PART + p] = pw * x0;
            d_soa[5 * N_PART + p] = pw * x1;
        }
    }
    gbar(3);

    // ---- P6: gather, f32x2-packed over particle pairs. 2 centroids/thread. ----
    {
        float alo, ahi, blo, bhi, clo, chi;
        upk(alo, ahi, sm.p.A2[tid]);
        upk(blo, bhi, sm.p.B2[tid]);
        upk(clo, chi, sm.p.C2[tid]);
        const u64 A0 = pk(alo, alo), B0 = pk(blo, blo), C0 = pk(clo, clo);
        const u64 A1 = pk(ahi, ahi), B1 = pk(bhi, bhi), C1 = pk(chi, chi);
        const int m0 = 2 * tid, m1 = 2 * tid + 1;
        u64 ax0 = 0, ay0 = 0, aw0 = 0, ax1 = 0, ay1 = 0, aw1 = 0;

        for (;;) {
            if (tid == 0) s_chunk = atomicAdd(&d_tick, 1u);
            __syncthreads();
            const unsigned c = s_chunk;
            if (c >= NCHUNK) break;
            if (tid < 192) {
                const int a = tid >> 5, e = tid & 31;
                s_buf[a * 32 + e] =
                    __ldcg(&((const float2*)(d_soa + a * N_PART))[c * 32 + e]);
            }
            __syncthreads();
            const u64* sb = (const u64*)s_buf;
#pragma unroll 2
            for (int j = 0; j < 32; ++j) {
                const u64 px2 = sb[j],        py2 = sb[32 + j],  pD2 = sb[64 + j];
                const u64 pw2 = sb[96 + j],   qx2 = sb[128 + j], qy2 = sb[160 + j];
                {
                    u64 u2 = add2(fma2(A0, px2, fma2(B0, py2, C0)), pD2);
                    float ua, ub; upk(ua, ub, u2);
                    u64 e2 = pk(fast_exp2(ua), fast_exp2(ub));
                    ax0 = fma2(e2, qx2, ax0);
                    ay0 = fma2(e2, qy2, ay0);
                    aw0 = fma2(e2, pw2, aw0);
                }
                {
                    u64 u2 = add2(fma2(A1, px2, fma2(B1, py2, C1)), pD2);
                    float ua, ub; upk(ua, ub, u2);
                    u64 e2 = pk(fast_exp2(ua), fast_exp2(ub));
                    ax1 = fma2(e2, qx2, ax1);
                    ay1 = fma2(e2, qy2, ay1);
                    aw1 = fma2(e2, pw2, aw1);
                }
            }
            __syncthreads();
        }
        float la, lb;
        upk(la, lb, ax0); atomicAdd(&d_acc[m0], la + lb);
        upk(la, lb, ay0); atomicAdd(&d_acc[N_CENT + m0], la + lb);
        upk(la, lb, aw0); atomicAdd(&d_acc[2 * N_CENT + m0], la + lb);
        upk(la, lb, ax1); atomicAdd(&d_acc[m1], la + lb);
        upk(la, lb, ay1); atomicAdd(&d_acc[N_CENT + m1], la + lb);
        upk(la, lb, aw1); atomicAdd(&d_acc[2 * N_CENT + m1], la + lb);
    }
    gbar(4);

    // ---- P7: finalize + re-zero scratch for the next graph replay ----
    if (gid < N_CENT) {
        float nx = __ldcg(&d_acc[gid]);
        float ny = __ldcg(&d_acc[N_CENT + gid]);
        float dn = __ldcg(&d_acc[2 * N_CENT + gid]);
        out[2 * gid + 0] = nx / dn;
        out[2 * gid + 1] = ny / dn;
        out[2 * N_CENT + gid] = dn;
    }
    if (gid < NBINS) d_hist[gid] = 0u;
    if (gid == NBINS) { d_gcnt = 0u; d_tick = 0u; }
}

extern "C" void kernel_launch(void* const* d_in, const int* in_sizes, int n_in,
                              void* d_out, int out_size) {
    const float* x = (const float*)d_in[0];   // [32768, 2]
    const float* w = (const float*)d_in[1];   // [32768]
    float* out = (float*)d_out;               // 6144 floats: y (4096) then v (2048)

    k_all<<<G, B>>>(x, w, out);
}

// round 8
// speedup vs baseline: 2.2831x; 1.0656x over previous
#include <cuda_runtime.h>
#include <stdint.h>

#define N_PART 32768
#define N_CENT 2048
// SC = -log2(e)/tau, tau = 1e-3
#define SC_CONST (-1442.6950408889634f)
// cutoff: exp2(SC*d^2) < 2^-24 for d > RCUT  (RCUT^2 * 1442.695 > 24)
#define RCUT 0.1290f
#define G 148
#define B 1024
#define NBINS 8192      // weight-bits histogram (top 13 bits)
#define PBINS 1024      // particle y bins
#define CBINS 256       // centroid y bins
#define PPB 222         // ceil(N_PART / G)

typedef unsigned long long u64;

__device__ float d_ccx[N_CENT], d_ccy[N_CENT];       // rank-ordered centroid coords
__device__ __align__(16) float d_sA[N_CENT + 4];     // y-sorted centroid constants (+pad)
__device__ __align__(16) float d_sB[N_CENT + 4];
__device__ __align__(16) float d_sC[N_CENT + 4];
__device__ float d_scy[N_CENT];                      // y-sorted centroid y
__device__ unsigned d_srank[N_CENT];                 // sorted index -> top-k rank
__device__ float d_spx[N_PART], d_spy[N_PART], d_spw[N_PART];   // y-sorted particles
__device__ __align__(256) float d_soa[6 * N_PART];   // sorted records: x0|x1|D|pw|pwx|pwy
__device__ float d_acc[3 * N_CENT];                  // accX | accY | accW (sorted index)
__device__ u64 d_cand[4096];
__device__ unsigned d_gcnt, d_tick;
__device__ unsigned d_hist[NBINS];
__device__ unsigned d_phist[PBINS];
__device__ unsigned d_chist[CBINS];
__device__ unsigned d_poff[PBINS];
__device__ unsigned d_coff[CBINS];
__device__ unsigned d_bar[8];

union SmU {
    u64 keys[4096];                                  // 32 KB (rank phase)
    unsigned scan[1024];                             // scans (P2/P4)
    struct {                                         // Z phase (~30 KB)
        u64 A2[1026], B2[1026], C2[1026];
        unsigned binC[257];
        float zp[256][4];
    } z;
    struct {                                         // gather phase (~29 KB)
        u64 tile[1536];                              // 512 particles x 6 arrays (paired)
        float red[3072];                             // [16][64][3]
        unsigned pps[1025];
        unsigned c0[32];
        unsigned P[33];
    } g;
};

__device__ __forceinline__ float fast_exp2(float x) {
    float r;
    asm("ex2.approx.ftz.f32 %0, %1;" : "=f"(r) : "f"(x));
    return r;
}
__device__ __forceinline__ u64 pk(float lo, float hi) {
    u64 r; asm("mov.b64 %0, {%1, %2};" : "=l"(r) : "f"(lo), "f"(hi)); return r;
}
__device__ __forceinline__ void upk(float& lo, float& hi, u64 v) {
    asm("mov.b64 {%0, %1}, %2;" : "=f"(lo), "=f"(hi) : "l"(v));
}
__device__ __forceinline__ u64 fma2(u64 a, u64 b, u64 c) {
    u64 r; asm("fma.rn.f32x2 %0, %1, %2, %3;" : "=l"(r) : "l"(a), "l"(b), "l"(c)); return r;
}
__device__ __forceinline__ u64 add2(u64 a, u64 b) {
    u64 r; asm("add.rn.f32x2 %0, %1, %2;" : "=l"(r) : "l"(a), "l"(b)); return r;
}

// Software grid barrier; monotonic counter, graph-replay safe.
__device__ __forceinline__ void gbar(int id) {
    __syncthreads();
    if (threadIdx.x == 0) {
        __threadfence();
        unsigned my = atomicAdd(&d_bar[id], 1u) + 1u;
        unsigned tgt = ((my + G - 1u) / G) * G;
        while (*((volatile unsigned*)&d_bar[id]) < tgt) { }
        __threadfence();
    }
    __syncthreads();
}

__global__ void __launch_bounds__(B, 1) k_all(const float* __restrict__ x,
                                              const float* __restrict__ w,
                                              float* __restrict__ out) {
    __shared__ SmU sm;
    __shared__ unsigned s_tbin, s_chunk;

    const int tid = threadIdx.x;
    const int bid = blockIdx.x;
    const int gid = bid * B + tid;

    // ================= P1: histograms + zero scratch =================
    // d_hist/d_phist zeroed by previous run's tail (static init covers run 1).
    unsigned wb = 0;
    if (gid < N_PART) {
        wb = __float_as_uint(w[gid]);
        atomicAdd(&d_hist[wb >> 19], 1u);
        float py = ((const float2*)x)[gid].y;
        int pb = min(PBINS - 1, max(0, (int)(py * (float)PBINS)));
        atomicAdd(&d_phist[pb], 1u);
    }
    if (gid < 3 * N_CENT) d_acc[gid] = 0.0f;
    if (gid >= 6144 && gid < 6144 + PBINS) d_poff[gid - 6144] = 0u;
    if (gid >= 7168 && gid < 7168 + CBINS) d_coff[gid - 7168] = 0u;
    if (gid >= 7424 && gid < 7424 + CBINS) d_chist[gid - 7424] = 0u;
    if (gid == 7680) { d_gcnt = 0u; d_tick = 0u; }
    gbar(0);

    // ================= P2: w-threshold + compact + particle sort =================
    {   // redundant per-block suffix scan over w-hist -> threshold bin
        unsigned s = 0;
#pragma unroll
        for (int j = 0; j < NBINS / B; ++j) s += __ldcg(&d_hist[tid * (NBINS / B) + j]);
        sm.scan[tid] = s;
        __syncthreads();
        for (int off = 1; off < B; off <<= 1) {
            unsigned v = sm.scan[tid] + ((tid + off < B) ? sm.scan[tid + off] : 0u);
            __syncthreads();
            sm.scan[tid] = v;
            __syncthreads();
        }
        if (sm.scan[tid] >= N_CENT && (tid == B - 1 || sm.scan[tid + 1] < N_CENT)) {
            unsigned cum = (tid + 1 < B) ? sm.scan[tid + 1] : 0u;
            unsigned tb = (unsigned)(tid * (NBINS / B));
            for (int bin = tid * (NBINS / B) + NBINS / B - 1; bin >= tid * (NBINS / B); --bin) {
                cum += __ldcg(&d_hist[bin]);
                if (cum >= N_CENT) { tb = (unsigned)bin; break; }
            }
            s_tbin = tb;
        }
        __syncthreads();
    }
    const unsigned T = s_tbin << 19;
    __syncthreads();

    // compact candidates
    if (gid < N_PART && wb >= T) {
        unsigned p = atomicAdd(&d_gcnt, 1u);
        if (p < 4096u)
            d_cand[p] = ((u64)wb << 32) | (unsigned)(~gid);
    }

    {   // particle y-bin exclusive prefix (redundant per block), then scatter
        unsigned h = __ldcg(&d_phist[tid]);
        sm.scan[tid] = h;
        __syncthreads();
        for (int off = 1; off < PBINS; off <<= 1) {
            unsigned add = (tid >= off) ? sm.scan[tid - off] : 0u;
            __syncthreads();
            sm.scan[tid] += add;
            __syncthreads();
        }
        unsigned excl = sm.scan[tid] - h;
        __syncthreads();
        sm.scan[tid] = excl;
        __syncthreads();
        if (gid < N_PART) {
            float2 xn = ((const float2*)x)[gid];
            float wn = w[gid];
            int pb = min(PBINS - 1, max(0, (int)(xn.y * (float)PBINS)));
            unsigned pos = sm.scan[pb] + atomicAdd(&d_poff[pb], 1u);
            d_spx[pos] = xn.x;
            d_spy[pos] = xn.y;
            d_spw[pos] = wn;
        }
    }
    gbar(1);

    // ================= P3: exact rank -> rank-ordered coords + centroid y-hist ====
    {
        const unsigned C = min(__ldcg(&d_gcnt), 4096u);
        for (int j = tid; j < (int)C; j += B) sm.keys[j] = __ldcg(&d_cand[j]);
        __syncthreads();
        const int lane = tid & 31;
        const int ws = bid * (B / 32) + (tid >> 5);
        for (int c = ws; c < (int)C; c += G * (B / 32)) {
            const u64 key = sm.keys[c];
            int r = 0;
            for (int j = lane; j < (int)C; j += 32) r += (sm.keys[j] > key);
            r = __reduce_add_sync(0xffffffffu, r);
            if (lane == 0 && r < N_CENT) {
                unsigned idx = ~((unsigned)(key & 0xFFFFFFFFull));
                float cx = x[2 * idx], cy = x[2 * idx + 1];
                d_ccx[r] = cx;
                d_ccy[r] = cy;
                int cb = min(CBINS - 1, max(0, (int)(cy * (float)CBINS)));
                atomicAdd(&d_chist[cb], 1u);
            }
        }
    }
    gbar(2);

    // ================= P4: centroid sort (bin prefix + scatter) + pad ============
    {
        unsigned h = (tid < CBINS) ? __ldcg(&d_chist[tid]) : 0u;
        if (tid < CBINS) sm.scan[tid] = h;
        __syncthreads();
        for (int off = 1; off < CBINS; off <<= 1) {
            unsigned add = (tid < CBINS && tid >= off) ? sm.scan[tid - off] : 0u;
            __syncthreads();
            if (tid < CBINS) sm.scan[tid] += add;
            __syncthreads();
        }
        unsigned excl = (tid < CBINS) ? sm.scan[tid] - h : 0u;
        __syncthreads();
        if (tid < CBINS) sm.scan[tid] = excl;
        __syncthreads();
        if (gid < N_CENT) {
            float cx = __ldcg(&d_ccx[gid]), cy = __ldcg(&d_ccy[gid]);
            int cb = min(CBINS - 1, max(0, (int)(cy * (float)CBINS)));
            unsigned pos = sm.scan[cb] + atomicAdd(&d_coff[cb], 1u);
            d_sA[pos] = SC_CONST * (-2.0f * cx);
            d_sB[pos] = SC_CONST * (-2.0f * cy);
            d_sC[pos] = SC_CONST * (cx * cx + cy * cy);
            d_scy[pos] = cy;
            d_srank[pos] = (unsigned)gid;
        }
        if (gid >= N_CENT && gid < N_CENT + 4) {   // pad: contributes exactly 0
            d_sA[gid] = 0.0f; d_sB[gid] = 0.0f; d_sC[gid] = -100000.0f;
        }
    }
    gbar(3);

    // ================= P5: Z pass with pruned, warp-uniform centroid range ========
    {
        for (int k = tid; k < 1026; k += B) {
            sm.z.A2[k] = pk(__ldcg(&d_sA[2 * k]), __ldcg(&d_sA[2 * k + 1]));
            sm.z.B2[k] = pk(__ldcg(&d_sB[2 * k]), __ldcg(&d_sB[2 * k + 1]));
            sm.z.C2[k] = pk(__ldcg(&d_sC[2 * k]), __ldcg(&d_sC[2 * k + 1]));
        }
        // centroid bin start table (exclusive prefix of chist)
        unsigned hC = (tid < CBINS) ? __ldcg(&d_chist[tid]) : 0u;
        if (tid < CBINS) sm.z.binC[tid] = hC;
        __syncthreads();
        for (int off = 1; off < CBINS; off <<= 1) {
            unsigned add = (tid < CBINS && tid >= off) ? sm.z.binC[tid - off] : 0u;
            __syncthreads();
            if (tid < CBINS) sm.z.binC[tid] += add;
            __syncthreads();
        }
        unsigned excl = (tid < CBINS) ? sm.z.binC[tid] - hC : 0u;
        __syncthreads();
        if (tid < CBINS) sm.z.binC[tid] = excl;
        if (tid == 0) sm.z.binC[CBINS] = N_CENT;
        __syncthreads();

        const int local = tid & 255;
        const int q = tid >> 8;
        const int base = bid * PPB;
        const int cnt = min(PPB, N_PART - base);
        const bool act = (local < cnt);
        const int j = base + local;
        float px = 0.f, py = 0.f, pwin = 0.f;
        int lo = 0x7fffffff, hi = 0;
        if (act) {
            px = __ldcg(&d_spx[j]);
            py = __ldcg(&d_spy[j]);
            pwin = __ldcg(&d_spw[j]);
            int bl = min(CBINS - 1, max(0, (int)((py - RCUT) * (float)CBINS)));
            int bh = min(CBINS, max(1, (int)((py + RCUT) * (float)CBINS) + 1));
            lo = (int)sm.z.binC[bl];
            hi = (int)sm.z.binC[bh];
        }
        int lo_w = __reduce_min_sync(0xffffffffu, lo);
        int hi_w = __reduce_max_sync(0xffffffffu, hi);
        if (lo_w > hi_w) { lo_w = 0; hi_w = 0; }
        const int len = hi_w - lo_w;
        const int k0 = (lo_w + ((len * q) >> 2)) >> 1;
        const int k1 = (q == 3) ? ((hi_w + 1) >> 1)
                                : ((lo_w + ((len * (q + 1)) >> 2)) >> 1);

        const float D = SC_CONST * (px * px + py * py);
        const u64 xx0 = pk(px, px), xx1 = pk(py, py), DD = pk(D, D);
        u64 za = 0, zb = 0;
        int k = k0;
        for (; k + 1 < k1; k += 2) {
            u64 u2a = fma2(sm.z.A2[k], xx0, fma2(sm.z.B2[k], xx1, add2(sm.z.C2[k], DD)));
            u64 u2b = fma2(sm.z.A2[k + 1], xx0, fma2(sm.z.B2[k + 1], xx1, add2(sm.z.C2[k + 1], DD)));
            float ua, ub, uc, ud;
            upk(ua, ub, u2a);
            upk(uc, ud, u2b);
            za = add2(za, pk(fast_exp2(ua), fast_exp2(ub)));
            zb = add2(zb, pk(fast_exp2(uc), fast_exp2(ud)));
        }
        if (k < k1) {
            u64 u2a = fma2(sm.z.A2[k], xx0, fma2(sm.z.B2[k], xx1, add2(sm.z.C2[k], DD)));
            float ua, ub;
            upk(ua, ub, u2a);
            za = add2(za, pk(fast_exp2(ua), fast_exp2(ub)));
        }
        if (act) {
            float s0, s1, s2, s3;
            upk(s0, s1, za);
            upk(s2, s3, zb);
            sm.z.zp[local][q] = (s0 + s1) + (s2 + s3);
        }
        __syncthreads();
        if (act && q == 0) {
            const float Z = sm.z.zp[local][0] + sm.z.zp[local][1]
                          + sm.z.zp[local][2] + sm.z.zp[local][3];
            const float pw = pwin / Z;
            d_soa[0 * N_PART + j] = px;
            d_soa[1 * N_PART + j] = py;
            d_soa[2 * N_PART + j] = D;
            d_soa[3 * N_PART + j] = pw;
            d_soa[4 * N_PART + j] = pw * px;
            d_soa[5 * N_PART + j] = pw * py;
        }
    }
    gbar(4);

    // ================= P6: banded gather (64 cents x 512-particle chunks) =========
    {
        // particle bin start table (exclusive prefix of phist)
        unsigned h = __ldcg(&d_phist[tid]);
        sm.g.pps[tid] = h;
        __syncthreads();
        for (int off = 1; off < PBINS; off <<= 1) {
            unsigned add = (tid >= off) ? sm.g.pps[tid - off] : 0u;
            __syncthreads();
            sm.g.pps[tid] += add;
            __syncthreads();
        }
        unsigned excl = sm.g.pps[tid] - h;
        __syncthreads();
        sm.g.pps[tid] = excl;
        if (tid == 0) sm.g.pps[PBINS] = N_PART;
        __syncthreads();

        // band -> chunk ranges (conservative via bins)
        if (tid < 32) {
            int B0 = min(CBINS - 1, max(0, (int)(__ldcg(&d_scy[64 * tid]) * (float)CBINS)));
            int B1 = min(CBINS - 1, max(0, (int)(__ldcg(&d_scy[64 * tid + 63]) * (float)CBINS)));
            float yl = (float)B0 * (1.0f / CBINS) - RCUT;
            float yh = (float)(B1 + 1) * (1.0f / CBINS) + RCUT;
            int bl = min(PBINS - 1, max(0, (int)(yl * (float)PBINS)));
            int bh = min(PBINS, max(1, (int)(yh * (float)PBINS) + 1));
            unsigned jlo = sm.g.pps[bl], jhi = sm.g.pps[bh];
            unsigned cc0 = jlo >> 9;
            unsigned cc1 = (jhi + 511u) >> 9;
            sm.g.c0[tid] = cc0;
            sm.g.P[tid] = cc1 - cc0;    // temp: count
        }
        __syncthreads();
        if (tid == 0) {
            unsigned run = 0;
            for (int b2 = 0; b2 < 32; ++b2) {
                unsigned t2 = sm.g.P[b2];
                sm.g.P[b2] = run;
                run += t2;
            }
            sm.g.P[32] = run;
        }
        __syncthreads();
        const unsigned ntiles = sm.g.P[32];

        const int c = tid & 63;
        const int s = tid >> 6;
        for (;;) {
            if (tid == 0) s_chunk = atomicAdd(&d_tick, 1u);
            __syncthreads();
            const unsigned t = s_chunk;
            if (t >= ntiles) break;
            int b = 0;
            while (sm.g.P[b + 1] <= t) ++b;
            const int ch = (int)sm.g.c0[b] + (int)(t - sm.g.P[b]);

            for (int i = tid; i < 1536; i += B) {
                const int a = i >> 8, e = i & 255;
                sm.g.tile[a * 256 + e] =
                    __ldcg(&((const u64*)(d_soa + a * N_PART))[ch * 256 + e]);
            }
            __syncthreads();

            const int m = 64 * b + c;
            const float cA = __ldcg(&d_sA[m]), cB = __ldcg(&d_sB[m]), cC = __ldcg(&d_sC[m]);
            const u64 A2c = pk(cA, cA), B2c = pk(cB, cB), C2c = pk(cC, cC);
            u64 ax = 0, ay = 0, aw = 0;
#pragma unroll 4
            for (int i = 0; i < 16; ++i) {
                const int e = s * 16 + i;
                const u64 px2 = sm.g.tile[e],        py2 = sm.g.tile[256 + e];
                const u64 pD2 = sm.g.tile[512 + e],  pw2 = sm.g.tile[768 + e];
                const u64 qx2 = sm.g.tile[1024 + e], qy2 = sm.g.tile[1280 + e];
                u64 u2 = fma2(A2c, px2, fma2(B2c, py2, add2(C2c, pD2)));
                float ua, ub;
                upk(ua, ub, u2);
                u64 e2 = pk(fast_exp2(ua), fast_exp2(ub));
                ax = fma2(e2, qx2, ax);
                ay = fma2(e2, qy2, ay);
                aw = fma2(e2, pw2, aw);
            }
            float la, lb;
            upk(la, lb, ax); sm.g.red[(s * 64 + c) * 3 + 0] = la + lb;
            upk(la, lb, ay); sm.g.red[(s * 64 + c) * 3 + 1] = la + lb;
            upk(la, lb, aw); sm.g.red[(s * 64 + c) * 3 + 2] = la + lb;
            __syncthreads();
            if (tid < 192) {
                const int cc = tid & 63, comp = tid >> 6;
                float sum = 0.f;
#pragma unroll
                for (int s2 = 0; s2 < 16; ++s2) sum += sm.g.red[(s2 * 64 + cc) * 3 + comp];
                atomicAdd(&d_acc[comp * N_CENT + 64 * b + cc], sum);
            }
            // loop-top __syncthreads() protects tile/red reuse
        }
    }
    gbar(5);

    // ================= P7: finalize (sorted -> rank order) + rezero ==============
    if (gid < N_CENT) {
        unsigned r = __ldcg(&d_srank[gid]);
        float ax = __ldcg(&d_acc[gid]);
        float ay = __ldcg(&d_acc[N_CENT + gid]);
        float aw = __ldcg(&d_acc[2 * N_CENT + gid]);
        out[2 * r + 0] = ax / aw;
        out[2 * r + 1] = ay / aw;
        out[2 * N_CENT + r] = aw;
    }
    if (gid < NBINS) d_hist[gid] = 0u;
    if (gid >= NBINS && gid < NBINS + PBINS) d_phist[gid - NBINS] = 0u;
}

extern "C" void kernel_launch(void* const* d_in, const int* in_sizes, int n_in,
                              void* d_out, int out_size) {
    const float* x = (const float*)d_in[0];   // [32768, 2]
    const float* w = (const float*)d_in[1];   // [32768]
    float* out = (float*)d_out;               // 6144 floats: y (4096) then v (2048)

    k_all<<<G, B>>>(x, w, out);
}

// round 9
// speedup vs baseline: 2.4339x; 1.0661x over previous
#include <cuda_runtime.h>
#include <stdint.h>

#define N_PART 32768
#define N_CENT 2048
// SC = -log2(e)/tau, tau = 1e-3
#define SC_CONST (-1442.6950408889634f)
// cutoff: exp2(SC*d^2) < 2^-24 for d > RCUT
#define RCUT 0.1290f
#define G 148
#define B 1024
#define NBINS 8192      // weight-bits histogram (top 13 bits)
#define PBINS 1024      // particle y bins
#define CBINS 256       // centroid y bins
#define PPB 222         // ceil(N_PART / G)

typedef unsigned long long u64;

__device__ float d_ccx[N_CENT], d_ccy[N_CENT];       // rank-ordered centroid coords
__device__ __align__(16) float d_sA[N_CENT + 4];     // y-sorted centroid constants (+pad)
__device__ __align__(16) float d_sB[N_CENT + 4];
__device__ __align__(16) float d_sC[N_CENT + 4];
__device__ float d_scy[N_CENT];                      // y-sorted centroid y
__device__ unsigned d_srank[N_CENT];                 // sorted index -> top-k rank
__device__ float d_spx[N_PART], d_spy[N_PART], d_spw[N_PART];   // y-sorted particles
__device__ __align__(256) float d_soa[6 * N_PART];   // sorted: x0|x1|D|pw|pwx|pwy
__device__ float d_acc[3 * N_CENT];                  // accX | accY | accW (sorted idx)
__device__ u64 d_cand[4096];
__device__ unsigned d_gcnt, d_tick;
__device__ unsigned d_hist[NBINS];
__device__ unsigned d_phist[PBINS];
__device__ unsigned d_chist[CBINS];
__device__ unsigned d_poff[PBINS];
__device__ unsigned d_coff[CBINS];
__device__ unsigned d_bar[8];

union SmU {
    u64 keys[4096];                                  // 32 KB (rank phase)
    unsigned scan[1024];                             // scans (P2/P4)
    struct {                                         // Z phase (~30 KB)
        u64 A2[1026], B2[1026], C2[1026];
        unsigned binC[257];
        float zp[256][4];
    } z;
    struct {                                         // gather phase (~42 KB)
        u64 tile[3072];                              // 1024 particles x 6 arrays
        float red[3072];                             // [16][64][3]
        unsigned pps[1025];
        unsigned c0[32];
        unsigned P[33];
        unsigned band[512];
    } g;
};

__device__ __forceinline__ float fast_exp2(float x) {
    float r;
    asm("ex2.approx.ftz.f32 %0, %1;" : "=f"(r) : "f"(x));
    return r;
}
__device__ __forceinline__ u64 pk(float lo, float hi) {
    u64 r; asm("mov.b64 %0, {%1, %2};" : "=l"(r) : "f"(lo), "f"(hi)); return r;
}
__device__ __forceinline__ void upk(float& lo, float& hi, u64 v) {
    asm("mov.b64 {%0, %1}, %2;" : "=f"(lo), "=f"(hi) : "l"(v));
}
__device__ __forceinline__ u64 fma2(u64 a, u64 b, u64 c) {
    u64 r; asm("fma.rn.f32x2 %0, %1, %2, %3;" : "=l"(r) : "l"(a), "l"(b), "l"(c)); return r;
}
__device__ __forceinline__ u64 add2(u64 a, u64 b) {
    u64 r; asm("add.rn.f32x2 %0, %1, %2;" : "=l"(r) : "l"(a), "l"(b)); return r;
}

__shared__ unsigned s_ws[32];

// Block-wide inclusive scan via warp shuffles: 3 barriers total.
__device__ __forceinline__ unsigned blockscan_incl(unsigned v) {
    const int lane = threadIdx.x & 31, wid = threadIdx.x >> 5;
    __syncthreads();                       // protect s_ws reuse
#pragma unroll
    for (int off = 1; off < 32; off <<= 1) {
        unsigned t = __shfl_up_sync(0xffffffffu, v, off);
        if (lane >= off) v += t;
    }
    if (lane == 31) s_ws[wid] = v;
    __syncthreads();
    if (wid == 0) {
        unsigned s = s_ws[lane];
#pragma unroll
        for (int off = 1; off < 32; off <<= 1) {
            unsigned t = __shfl_up_sync(0xffffffffu, s, off);
            if (lane >= off) s += t;
        }
        s_ws[lane] = s;
    }
    __syncthreads();
    if (wid > 0) v += s_ws[wid - 1];
    return v;
}

// Software grid barrier; monotonic counter, graph-replay safe.
__device__ __forceinline__ void gbar(int id) {
    __syncthreads();
    if (threadIdx.x == 0) {
        __threadfence();
        unsigned my = atomicAdd(&d_bar[id], 1u) + 1u;
        unsigned tgt = ((my + G - 1u) / G) * G;
        while (*((volatile unsigned*)&d_bar[id]) < tgt) { }
        __threadfence();
    }
    __syncthreads();
}

__global__ void __launch_bounds__(B, 1) k_all(const float* __restrict__ x,
                                              const float* __restrict__ w,
                                              float* __restrict__ out) {
    __shared__ SmU sm;
    __shared__ unsigned s_tbin, s_chunk, s_total;

    const int tid = threadIdx.x;
    const int bid = blockIdx.x;
    const int gid = bid * B + tid;

    // ================= P1: histograms + zero scratch =================
    unsigned wb = 0;
    if (gid < N_PART) {
        wb = __float_as_uint(w[gid]);
        atomicAdd(&d_hist[wb >> 19], 1u);
        float py = ((const float2*)x)[gid].y;
        int pb = min(PBINS - 1, max(0, (int)(py * (float)PBINS)));
        atomicAdd(&d_phist[pb], 1u);
    }
    if (gid < 3 * N_CENT) d_acc[gid] = 0.0f;
    if (gid >= 6144 && gid < 6144 + PBINS) d_poff[gid - 6144] = 0u;
    if (gid >= 7168 && gid < 7168 + CBINS) d_coff[gid - 7168] = 0u;
    if (gid >= 7424 && gid < 7424 + CBINS) d_chist[gid - 7424] = 0u;
    if (gid == 7680) { d_gcnt = 0u; d_tick = 0u; }
    gbar(0);

    // ================= P2: w-threshold + compact + particle sort =================
    {   // chunk sums -> prefix scan -> suffix condition
        unsigned s = 0;
#pragma unroll
        for (int j = 0; j < NBINS / B; ++j) s += __ldcg(&d_hist[tid * (NBINS / B) + j]);
        unsigned Pin = blockscan_incl(s);
        if (tid == B - 1) s_total = Pin;
        __syncthreads();
        const unsigned total = s_total;
        // suffix_incl(tid) = total - Pin + s ; suffix_incl(tid+1) = total - Pin
        if ((total - Pin + s) >= N_CENT && (total - Pin) < N_CENT) {
            unsigned cum = total - Pin;
            unsigned tb = (unsigned)(tid * (NBINS / B));
            for (int bin = tid * (NBINS / B) + NBINS / B - 1; bin >= tid * (NBINS / B); --bin) {
                cum += __ldcg(&d_hist[bin]);
                if (cum >= N_CENT) { tb = (unsigned)bin; break; }
            }
            s_tbin = tb;
        }
        __syncthreads();
    }
    const unsigned T = s_tbin << 19;

    // compact candidates
    if (gid < N_PART && wb >= T) {
        unsigned p = atomicAdd(&d_gcnt, 1u);
        if (p < 4096u)
            d_cand[p] = ((u64)wb << 32) | (unsigned)(~gid);
    }

    {   // particle y-bin exclusive prefix, then scatter
        unsigned h = __ldcg(&d_phist[tid]);
        unsigned excl = blockscan_incl(h) - h;
        sm.scan[tid] = excl;
        __syncthreads();
        if (gid < N_PART) {
            float2 xn = ((const float2*)x)[gid];
            float wn = w[gid];
            int pb = min(PBINS - 1, max(0, (int)(xn.y * (float)PBINS)));
            unsigned pos = sm.scan[pb] + atomicAdd(&d_poff[pb], 1u);
            d_spx[pos] = xn.x;
            d_spy[pos] = xn.y;
            d_spw[pos] = wn;
        }
    }
    gbar(1);

    // ================= P3: exact rank -> rank-ordered coords + centroid y-hist ====
    {
        const unsigned C = min(__ldcg(&d_gcnt), 4096u);
        for (int j = tid; j < (int)C; j += B) sm.keys[j] = __ldcg(&d_cand[j]);
        __syncthreads();
        const int lane = tid & 31;
        const int ws = bid * (B / 32) + (tid >> 5);
        for (int c = ws; c < (int)C; c += G * (B / 32)) {
            const u64 key = sm.keys[c];
            int r = 0;
            for (int j = lane; j < (int)C; j += 32) r += (sm.keys[j] > key);
            r = __reduce_add_sync(0xffffffffu, r);
            if (lane == 0 && r < N_CENT) {
                unsigned idx = ~((unsigned)(key & 0xFFFFFFFFull));
                float cx = x[2 * idx], cy = x[2 * idx + 1];
                d_ccx[r] = cx;
                d_ccy[r] = cy;
                int cb = min(CBINS - 1, max(0, (int)(cy * (float)CBINS)));
                atomicAdd(&d_chist[cb], 1u);
            }
        }
    }
    gbar(2);

    // ================= P4: centroid sort (bin prefix + scatter) + pad ============
    {
        unsigned h = (tid < CBINS) ? __ldcg(&d_chist[tid]) : 0u;
        unsigned excl = blockscan_incl(h) - h;
        if (tid < CBINS) sm.scan[tid] = excl;
        __syncthreads();
        if (gid < N_CENT) {
            float cx = __ldcg(&d_ccx[gid]), cy = __ldcg(&d_ccy[gid]);
            int cb = min(CBINS - 1, max(0, (int)(cy * (float)CBINS)));
            unsigned pos = sm.scan[cb] + atomicAdd(&d_coff[cb], 1u);
            d_sA[pos] = SC_CONST * (-2.0f * cx);
            d_sB[pos] = SC_CONST * (-2.0f * cy);
            d_sC[pos] = SC_CONST * (cx * cx + cy * cy);
            d_scy[pos] = cy;
            d_srank[pos] = (unsigned)gid;
        }
        if (gid >= N_CENT && gid < N_CENT + 4) {   // pad: contributes exactly 0
            d_sA[gid] = 0.0f; d_sB[gid] = 0.0f; d_sC[gid] = -100000.0f;
        }
    }
    gbar(3);

    // ================= P5: Z pass with pruned, warp-uniform centroid range ========
    {
        for (int k = tid; k < 1026; k += B) {
            float2 a = ((const float2*)d_sA)[k];
            float2 b = ((const float2*)d_sB)[k];
            float2 c = ((const float2*)d_sC)[k];
            sm.z.A2[k] = pk(a.x, a.y);
            sm.z.B2[k] = pk(b.x, b.y);
            sm.z.C2[k] = pk(c.x, c.y);
        }
        unsigned hC = (tid < CBINS) ? __ldcg(&d_chist[tid]) : 0u;
        unsigned exC = blockscan_incl(hC) - hC;
        if (tid < CBINS) sm.z.binC[tid] = exC;
        if (tid == 0) sm.z.binC[CBINS] = N_CENT;
        __syncthreads();

        const int local = tid & 255;
        const int q = tid >> 8;
        const int base = bid * PPB;
        const int cnt = min(PPB, N_PART - base);
        const bool act = (local < cnt);
        const int j = base + local;
        float px = 0.f, py = 0.f, pwin = 0.f;
        int lo = 0x7fffffff, hi = 0;
        if (act) {
            px = __ldcg(&d_spx[j]);
            py = __ldcg(&d_spy[j]);
            pwin = __ldcg(&d_spw[j]);
            int bl = min(CBINS - 1, max(0, (int)((py - RCUT) * (float)CBINS)));
            int bh = min(CBINS, max(1, (int)((py + RCUT) * (float)CBINS) + 1));
            lo = (int)sm.z.binC[bl];
            hi = (int)sm.z.binC[bh];
        }
        int lo_w = __reduce_min_sync(0xffffffffu, lo);
        int hi_w = __reduce_max_sync(0xffffffffu, hi);
        if (lo_w > hi_w) { lo_w = 0; hi_w = 0; }
        const int len = hi_w - lo_w;
        const int k0 = (lo_w + ((len * q) >> 2)) >> 1;
        const int k1 = (q == 3) ? ((hi_w + 1) >> 1)
                                : ((lo_w + ((len * (q + 1)) >> 2)) >> 1);

        const float D = SC_CONST * (px * px + py * py);
        const u64 xx0 = pk(px, px), xx1 = pk(py, py), DD = pk(D, D);
        u64 za = 0, zb = 0;
        int k = k0;
        for (; k + 1 < k1; k += 2) {
            u64 u2a = fma2(sm.z.A2[k], xx0, fma2(sm.z.B2[k], xx1, add2(sm.z.C2[k], DD)));
            u64 u2b = fma2(sm.z.A2[k + 1], xx0, fma2(sm.z.B2[k + 1], xx1, add2(sm.z.C2[k + 1], DD)));
            float ua, ub, uc, ud;
            upk(ua, ub, u2a);
            upk(uc, ud, u2b);
            za = add2(za, pk(fast_exp2(ua), fast_exp2(ub)));
            zb = add2(zb, pk(fast_exp2(uc), fast_exp2(ud)));
        }
        if (k < k1) {
            u64 u2a = fma2(sm.z.A2[k], xx0, fma2(sm.z.B2[k], xx1, add2(sm.z.C2[k], DD)));
            float ua, ub;
            upk(ua, ub, u2a);
            za = add2(za, pk(fast_exp2(ua), fast_exp2(ub)));
        }
        if (act) {
            float s0, s1, s2, s3;
            upk(s0, s1, za);
            upk(s2, s3, zb);
            sm.z.zp[local][q] = (s0 + s1) + (s2 + s3);
        }
        __syncthreads();
        if (act && q == 0) {
            const float Z = sm.z.zp[local][0] + sm.z.zp[local][1]
                          + sm.z.zp[local][2] + sm.z.zp[local][3];
            const float pw = pwin / Z;
            d_soa[0 * N_PART + j] = px;
            d_soa[1 * N_PART + j] = py;
            d_soa[2 * N_PART + j] = D;
            d_soa[3 * N_PART + j] = pw;
            d_soa[4 * N_PART + j] = pw * px;
            d_soa[5 * N_PART + j] = pw * py;
        }
    }
    gbar(4);

    // ================= P6: banded gather (64 cents x 1024-particle chunks) ========
    {
        unsigned h = __ldcg(&d_phist[tid]);
        unsigned excl = blockscan_incl(h) - h;
        sm.g.pps[tid] = excl;
        if (tid == 0) sm.g.pps[PBINS] = N_PART;
        __syncthreads();

        if (tid < 32) {
            int B0 = min(CBINS - 1, max(0, (int)(__ldcg(&d_scy[64 * tid]) * (float)CBINS)));
            int B1 = min(CBINS - 1, max(0, (int)(__ldcg(&d_scy[64 * tid + 63]) * (float)CBINS)));
            float yl = (float)B0 * (1.0f / CBINS) - RCUT;
            float yh = (float)(B1 + 1) * (1.0f / CBINS) + RCUT;
            int bl = min(PBINS - 1, max(0, (int)(yl * (float)PBINS)));
            int bh = min(PBINS, max(1, (int)(yh * (float)PBINS) + 1));
            unsigned jlo = sm.g.pps[bl], jhi = sm.g.pps[bh];
            sm.g.c0[tid] = jlo >> 10;
            sm.g.P[tid] = ((jhi + 1023u) >> 10) - (jlo >> 10);
        }
        __syncthreads();
        if (tid == 0) {
            unsigned run = 0;
            for (int b2 = 0; b2 < 32; ++b2) {
                unsigned t2 = sm.g.P[b2];
                sm.g.P[b2] = run;
                run += t2;
            }
            sm.g.P[32] = run;
        }
        __syncthreads();
        const unsigned ntiles = min(sm.g.P[32], 512u);
        for (unsigned t = tid; t < ntiles; t += B) {   // tile -> band map
            int lo2 = 0, hi2 = 31;
            while (lo2 < hi2) {
                int mid = (lo2 + hi2 + 1) >> 1;
                if (sm.g.P[mid] <= t) lo2 = mid; else hi2 = mid - 1;
            }
            sm.g.band[t] = (unsigned)lo2;
        }
        __syncthreads();

        const int c = tid & 63;
        const int s = tid >> 6;
        for (;;) {
            if (tid == 0) s_chunk = atomicAdd(&d_tick, 1u);
            __syncthreads();
            const unsigned t = s_chunk;
            if (t >= ntiles) break;
            const int b = (int)sm.g.band[t];
            const int ch = (int)sm.g.c0[b] + (int)(t - sm.g.P[b]);

            for (int i = tid; i < 3072; i += B) {
                const int a = i >> 9, e = i & 511;
                sm.g.tile[a * 512 + e] =
                    __ldcg(&((const u64*)(d_soa + a * N_PART))[ch * 512 + e]);
            }
            __syncthreads();

            const int m = 64 * b + c;
            const float cA = __ldcg(&d_sA[m]), cB = __ldcg(&d_sB[m]), cC = __ldcg(&d_sC[m]);
            const u64 A2c = pk(cA, cA), B2c = pk(cB, cB), C2c = pk(cC, cC);
            u64 ax = 0, ay = 0, aw = 0;
#pragma unroll 4
            for (int i = 0; i < 32; ++i) {
                const int e = s * 32 + i;
                const u64 px2 = sm.g.tile[e],         py2 = sm.g.tile[512 + e];
                const u64 pD2 = sm.g.tile[1024 + e],  pw2 = sm.g.tile[1536 + e];
                const u64 qx2 = sm.g.tile[2048 + e],  qy2 = sm.g.tile[2560 + e];
                u64 u2 = fma2(A2c, px2, fma2(B2c, py2, add2(C2c, pD2)));
                float ua, ub;
                upk(ua, ub, u2);
                u64 e2 = pk(fast_exp2(ua), fast_exp2(ub));
                ax = fma2(e2, qx2, ax);
                ay = fma2(e2, qy2, ay);
                aw = fma2(e2, pw2, aw);
            }
            float la, lb;
            upk(la, lb, ax); sm.g.red[(s * 64 + c) * 3 + 0] = la + lb;
            upk(la, lb, ay); sm.g.red[(s * 64 + c) * 3 + 1] = la + lb;
            upk(la, lb, aw); sm.g.red[(s * 64 + c) * 3 + 2] = la + lb;
            __syncthreads();
            if (tid < 192) {
                const int cc = tid & 63, comp = tid >> 6;
                float sum = 0.f;
#pragma unroll
                for (int s2 = 0; s2 < 16; ++s2) sum += sm.g.red[(s2 * 64 + cc) * 3 + comp];
                atomicAdd(&d_acc[comp * N_CENT + 64 * b + cc], sum);
            }
            __syncthreads();
        }
    }
    gbar(5);

    // ================= P7: finalize (sorted -> rank order) + rezero ==============
    if (gid < N_CENT) {
        unsigned r = __ldcg(&d_srank[gid]);
        float ax = __ldcg(&d_acc[gid]);
        float ay = __ldcg(&d_acc[N_CENT + gid]);
        float aw = __ldcg(&d_acc[2 * N_CENT + gid]);
        out[2 * r + 0] = ax / aw;
        out[2 * r + 1] = ay / aw;
        out[2 * N_CENT + r] = aw;
    }
    if (gid < NBINS) d_hist[gid] = 0u;
    if (gid >= NBINS && gid < NBINS + PBINS) d_phist[gid - NBINS] = 0u;
}

extern "C" void kernel_launch(void* const* d_in, const int* in_sizes, int n_in,
                              void* d_out, int out_size) {
    const float* x = (const float*)d_in[0];   // [32768, 2]
    const float* w = (const float*)d_in[1];   // [32768]
    float* out = (float*)d_out;               // 6144 floats: y (4096) then v (2048)

    k_all<<<G, B>>>(x, w, out);
}

// round 10
// speedup vs baseline: 2.4720x; 1.0157x over previous
#include <cuda_runtime.h>
#include <stdint.h>

#define N_PART 32768
#define N_CENT 2048
// SC = -log2(e)/tau, tau = 1e-3
#define SC_CONST (-1442.6950408889634f)
// cutoff: exp2(SC*d^2) < 2^-24 for d > RCUT
#define RCUT 0.1290f
#define G 148
#define B 1024
#define NBINS 8192      // weight-bits histogram (top 13 bits)
#define PBINS 1024      // particle y bins
#define CBINS 256       // centroid y bins
#define PPB 222         // ceil(N_PART / G)

typedef unsigned long long u64;

__device__ float d_ccx[N_CENT], d_ccy[N_CENT];       // rank-ordered centroid coords
__device__ __align__(16) float d_sA[N_CENT + 4];     // y-sorted centroid constants (+pad)
__device__ __align__(16) float d_sB[N_CENT + 4];
__device__ __align__(16) float d_sC[N_CENT + 4];
__device__ float d_scy[N_CENT];                      // y-sorted centroid y
__device__ unsigned d_srank[N_CENT];                 // sorted index -> top-k rank
__device__ float d_spx[N_PART], d_spy[N_PART], d_spw[N_PART];   // y-sorted particles
__device__ __align__(256) float d_soa[6 * N_PART];   // sorted: x0|x1|D|pw|pwx|pwy
__device__ float d_acc[3 * N_CENT];                  // accX | accY | accW (sorted idx)
__device__ u64 d_cand[4096];
__device__ unsigned d_gcnt, d_tick;
__device__ unsigned d_hist[NBINS];
__device__ unsigned d_phist[PBINS];
__device__ unsigned d_chist[CBINS];
__device__ unsigned d_poff[PBINS];
__device__ unsigned d_coff[CBINS];
__device__ unsigned d_bar[8];

union __align__(16) SmU {
    u64 keys[4096];                                  // 32 KB (rank phase)
    unsigned scan[1024];                             // scans (P2/P4)
    struct {                                         // Z phase (~30 KB)
        u64 A2[1026], B2[1026], C2[1026];
        unsigned binC[257];
        float zp[256][4];
    } z;
    struct {                                         // gather phase (~42 KB)
        u64 tile[3072];                              // 1024 particles x 6 arrays
        float red[3072];                             // [16][64][3]
        unsigned pps[1025];
        unsigned c0[32];
        unsigned P[33];
        unsigned band[512];
    } g;
};

__device__ __forceinline__ float fast_exp2(float x) {
    float r;
    asm("ex2.approx.ftz.f32 %0, %1;" : "=f"(r) : "f"(x));
    return r;
}
__device__ __forceinline__ u64 pk(float lo, float hi) {
    u64 r; asm("mov.b64 %0, {%1, %2};" : "=l"(r) : "f"(lo), "f"(hi)); return r;
}
__device__ __forceinline__ void upk(float& lo, float& hi, u64 v) {
    asm("mov.b64 {%0, %1}, %2;" : "=f"(lo), "=f"(hi) : "l"(v));
}
__device__ __forceinline__ u64 fma2(u64 a, u64 b, u64 c) {
    u64 r; asm("fma.rn.f32x2 %0, %1, %2, %3;" : "=l"(r) : "l"(a), "l"(b), "l"(c)); return r;
}
__device__ __forceinline__ u64 add2(u64 a, u64 b) {
    u64 r; asm("add.rn.f32x2 %0, %1, %2;" : "=l"(r) : "l"(a), "l"(b)); return r;
}

__shared__ unsigned s_ws[32];

// Block-wide inclusive scan via warp shuffles: 3 barriers total.
__device__ __forceinline__ unsigned blockscan_incl(unsigned v) {
    const int lane = threadIdx.x & 31, wid = threadIdx.x >> 5;
    __syncthreads();                       // protect s_ws reuse
#pragma unroll
    for (int off = 1; off < 32; off <<= 1) {
        unsigned t = __shfl_up_sync(0xffffffffu, v, off);
        if (lane >= off) v += t;
    }
    if (lane == 31) s_ws[wid] = v;
    __syncthreads();
    if (wid == 0) {
        unsigned s = s_ws[lane];
#pragma unroll
        for (int off = 1; off < 32; off <<= 1) {
            unsigned t = __shfl_up_sync(0xffffffffu, s, off);
            if (lane >= off) s += t;
        }
        s_ws[lane] = s;
    }
    __syncthreads();
    if (wid > 0) v += s_ws[wid - 1];
    return v;
}

// Software grid barrier; monotonic counter, graph-replay safe.
__device__ __forceinline__ void gbar(int id) {
    __syncthreads();
    if (threadIdx.x == 0) {
        __threadfence();
        unsigned my = atomicAdd(&d_bar[id], 1u) + 1u;
        unsigned tgt = ((my + G - 1u) / G) * G;
        while (*((volatile unsigned*)&d_bar[id]) < tgt) { }
        __threadfence();
    }
    __syncthreads();
}

__global__ void __launch_bounds__(B, 1) k_all(const float* __restrict__ x,
                                              const float* __restrict__ w,
                                              float* __restrict__ out) {
    __shared__ SmU sm;
    __shared__ unsigned s_tbin, s_chunk, s_total;

    const int tid = threadIdx.x;
    const int bid = blockIdx.x;
    const int gid = bid * B + tid;

    // ================= P1: histograms + zero scratch =================
    unsigned wb = 0;
    if (gid < N_PART) {
        wb = __float_as_uint(w[gid]);
        atomicAdd(&d_hist[wb >> 19], 1u);
        float py = ((const float2*)x)[gid].y;
        int pb = min(PBINS - 1, max(0, (int)(py * (float)PBINS)));
        atomicAdd(&d_phist[pb], 1u);
    }
    if (gid < 3 * N_CENT) d_acc[gid] = 0.0f;
    if (gid >= 6144 && gid < 6144 + PBINS) d_poff[gid - 6144] = 0u;
    if (gid >= 7168 && gid < 7168 + CBINS) d_coff[gid - 7168] = 0u;
    if (gid >= 7424 && gid < 7424 + CBINS) d_chist[gid - 7424] = 0u;
    if (gid == 7680) { d_gcnt = 0u; d_tick = 0u; }
    gbar(0);

    // ================= P2: w-threshold + compact + particle sort =================
    {   // chunk sums -> prefix scan -> suffix condition
        unsigned s = 0;
#pragma unroll
        for (int j = 0; j < NBINS / B; ++j) s += __ldcg(&d_hist[tid * (NBINS / B) + j]);
        unsigned Pin = blockscan_incl(s);
        if (tid == B - 1) s_total = Pin;
        __syncthreads();
        const unsigned total = s_total;
        if ((total - Pin + s) >= N_CENT && (total - Pin) < N_CENT) {
            unsigned cum = total - Pin;
            unsigned tb = (unsigned)(tid * (NBINS / B));
            for (int bin = tid * (NBINS / B) + NBINS / B - 1; bin >= tid * (NBINS / B); --bin) {
                cum += __ldcg(&d_hist[bin]);
                if (cum >= N_CENT) { tb = (unsigned)bin; break; }
            }
            s_tbin = tb;
        }
        __syncthreads();
    }
    const unsigned T = s_tbin << 19;

    // compact candidates
    if (gid < N_PART && wb >= T) {
        unsigned p = atomicAdd(&d_gcnt, 1u);
        if (p < 4096u)
            d_cand[p] = ((u64)wb << 32) | (unsigned)(~gid);
    }

    {   // particle y-bin exclusive prefix, then scatter
        unsigned h = __ldcg(&d_phist[tid]);
        unsigned excl = blockscan_incl(h) - h;
        sm.scan[tid] = excl;
        __syncthreads();
        if (gid < N_PART) {
            float2 xn = ((const float2*)x)[gid];
            float wn = w[gid];
            int pb = min(PBINS - 1, max(0, (int)(xn.y * (float)PBINS)));
            unsigned pos = sm.scan[pb] + atomicAdd(&d_poff[pb], 1u);
            d_spx[pos] = xn.x;
            d_spy[pos] = xn.y;
            d_spw[pos] = wn;
        }
    }
    gbar(1);

    // ================= P3: exact rank -> rank-ordered coords + centroid y-hist ====
    {
        const unsigned C = min(__ldcg(&d_gcnt), 4096u);
        for (int j = tid; j < (int)C; j += B) sm.keys[j] = __ldcg(&d_cand[j]);
        __syncthreads();
        const int lane = tid & 31;
        const int ws = bid * (B / 32) + (tid >> 5);
        for (int c = ws; c < (int)C; c += G * (B / 32)) {
            const u64 key = sm.keys[c];
            int r = 0;
            for (int j = lane; j < (int)C; j += 32) r += (sm.keys[j] > key);
            r = __reduce_add_sync(0xffffffffu, r);
            if (lane == 0 && r < N_CENT) {
                unsigned idx = ~((unsigned)(key & 0xFFFFFFFFull));
                float cx = x[2 * idx], cy = x[2 * idx + 1];
                d_ccx[r] = cx;
                d_ccy[r] = cy;
                int cb = min(CBINS - 1, max(0, (int)(cy * (float)CBINS)));
                atomicAdd(&d_chist[cb], 1u);
            }
        }
    }
    gbar(2);

    // ================= P4: centroid sort (bin prefix + scatter) + pad ============
    {
        unsigned h = (tid < CBINS) ? __ldcg(&d_chist[tid]) : 0u;
        unsigned excl = blockscan_incl(h) - h;
        if (tid < CBINS) sm.scan[tid] = excl;
        __syncthreads();
        if (gid < N_CENT) {
            float cx = __ldcg(&d_ccx[gid]), cy = __ldcg(&d_ccy[gid]);
            int cb = min(CBINS - 1, max(0, (int)(cy * (float)CBINS)));
            unsigned pos = sm.scan[cb] + atomicAdd(&d_coff[cb], 1u);
            d_sA[pos] = SC_CONST * (-2.0f * cx);
            d_sB[pos] = SC_CONST * (-2.0f * cy);
            d_sC[pos] = SC_CONST * (cx * cx + cy * cy);
            d_scy[pos] = cy;
            d_srank[pos] = (unsigned)gid;
        }
        if (gid >= N_CENT && gid < N_CENT + 4) {   // pad: contributes exactly 0
            d_sA[gid] = 0.0f; d_sB[gid] = 0.0f; d_sC[gid] = -100000.0f;
        }
    }
    gbar(3);

    // ================= P5: Z pass, pruned + LDS.128 (even-pair groups) ============
    {
        // stage packed centroid constants: float4 loads, STS.128 stores
        for (int k = tid; k < 513; k += B) {
            float4 a = ((const float4*)d_sA)[k];
            float4 b = ((const float4*)d_sB)[k];
            float4 c = ((const float4*)d_sC)[k];
            ulonglong2 av; av.x = pk(a.x, a.y); av.y = pk(a.z, a.w);
            ulonglong2 bv; bv.x = pk(b.x, b.y); bv.y = pk(b.z, b.w);
            ulonglong2 cv; cv.x = pk(c.x, c.y); cv.y = pk(c.z, c.w);
            *(ulonglong2*)&sm.z.A2[2 * k] = av;
            *(ulonglong2*)&sm.z.B2[2 * k] = bv;
            *(ulonglong2*)&sm.z.C2[2 * k] = cv;
        }
        unsigned hC = (tid < CBINS) ? __ldcg(&d_chist[tid]) : 0u;
        unsigned exC = blockscan_incl(hC) - hC;
        if (tid < CBINS) sm.z.binC[tid] = exC;
        if (tid == 0) sm.z.binC[CBINS] = N_CENT;
        __syncthreads();

        const int local = tid & 255;
        const int q = tid >> 8;
        const int base = bid * PPB;
        const int cnt = min(PPB, N_PART - base);
        const bool act = (local < cnt);
        const int j = base + local;
        float px = 0.f, py = 0.f, pwin = 0.f;
        int lo = 0x7fffffff, hi = 0;
        if (act) {
            px = __ldcg(&d_spx[j]);
            py = __ldcg(&d_spy[j]);
            pwin = __ldcg(&d_spw[j]);
            int bl = min(CBINS - 1, max(0, (int)((py - RCUT) * (float)CBINS)));
            int bh = min(CBINS, max(1, (int)((py + RCUT) * (float)CBINS) + 1));
            lo = (int)sm.z.binC[bl];
            hi = (int)sm.z.binC[bh];
        }
        int lo_w = __reduce_min_sync(0xffffffffu, lo);
        int hi_w = __reduce_max_sync(0xffffffffu, hi);
        if (lo_w > hi_w) { lo_w = 0; hi_w = 0; }
        // even-pair (4-centroid) group grid; exact partition across q,
        // grid rounding adds only beyond-RCUT cents (each < 2^-24)
        const int s_pi = lo_w >> 1;
        const int e_pi = (hi_w + 1) >> 1;
        const int s2 = s_pi >> 1;
        const int e2 = (e_pi + 1) >> 1;
        const int ng = e2 - s2;
        const int g0 = s2 + ((ng * q) >> 2);
        const int g1 = s2 + ((ng * (q + 1)) >> 2);

        const float D = SC_CONST * (px * px + py * py);
        const u64 xx0 = pk(px, px), xx1 = pk(py, py), DD = pk(D, D);
        u64 za = 0, zb = 0;
#pragma unroll 2
        for (int g = g0; g < g1; ++g) {
            ulonglong2 a = *(const ulonglong2*)&sm.z.A2[2 * g];
            ulonglong2 b = *(const ulonglong2*)&sm.z.B2[2 * g];
            ulonglong2 c = *(const ulonglong2*)&sm.z.C2[2 * g];
            u64 u2a = fma2(a.x, xx0, fma2(b.x, xx1, add2(c.x, DD)));
            u64 u2b = fma2(a.y, xx0, fma2(b.y, xx1, add2(c.y, DD)));
            float ua, ub, uc, ud;
            upk(ua, ub, u2a);
            upk(uc, ud, u2b);
            za = add2(za, pk(fast_exp2(ua), fast_exp2(ub)));
            zb = add2(zb, pk(fast_exp2(uc), fast_exp2(ud)));
        }
        if (act) {
            float s0, s1, s2f, s3;
            upk(s0, s1, za);
            upk(s2f, s3, zb);
            sm.z.zp[local][q] = (s0 + s1) + (s2f + s3);
        }
        __syncthreads();
        if (act && q == 0) {
            const float Z = sm.z.zp[local][0] + sm.z.zp[local][1]
                          + sm.z.zp[local][2] + sm.z.zp[local][3];
            const float pw = pwin / Z;
            d_soa[0 * N_PART + j] = px;
            d_soa[1 * N_PART + j] = py;
            d_soa[2 * N_PART + j] = D;
            d_soa[3 * N_PART + j] = pw;
            d_soa[4 * N_PART + j] = pw * px;
            d_soa[5 * N_PART + j] = pw * py;
        }
    }
    gbar(4);

    // ================= P6: banded gather, LDS.128 pairwise tile reads =============
    {
        unsigned h = __ldcg(&d_phist[tid]);
        unsigned excl = blockscan_incl(h) - h;
        sm.g.pps[tid] = excl;
        if (tid == 0) sm.g.pps[PBINS] = N_PART;
        __syncthreads();

        if (tid < 32) {
            int B0 = min(CBINS - 1, max(0, (int)(__ldcg(&d_scy[64 * tid]) * (float)CBINS)));
            int B1 = min(CBINS - 1, max(0, (int)(__ldcg(&d_scy[64 * tid + 63]) * (float)CBINS)));
            float yl = (float)B0 * (1.0f / CBINS) - RCUT;
            float yh = (float)(B1 + 1) * (1.0f / CBINS) + RCUT;
            int bl = min(PBINS - 1, max(0, (int)(yl * (float)PBINS)));
            int bh = min(PBINS, max(1, (int)(yh * (float)PBINS) + 1));
            unsigned jlo = sm.g.pps[bl], jhi = sm.g.pps[bh];
            sm.g.c0[tid] = jlo >> 10;
            sm.g.P[tid] = ((jhi + 1023u) >> 10) - (jlo >> 10);
        }
        __syncthreads();
        if (tid == 0) {
            unsigned run = 0;
            for (int b2 = 0; b2 < 32; ++b2) {
                unsigned t2 = sm.g.P[b2];
                sm.g.P[b2] = run;
                run += t2;
            }
            sm.g.P[32] = run;
        }
        __syncthreads();
        const unsigned ntiles = min(sm.g.P[32], 512u);
        for (unsigned t = tid; t < ntiles; t += B) {   // tile -> band map
            int lo2 = 0, hi2 = 31;
            while (lo2 < hi2) {
                int mid = (lo2 + hi2 + 1) >> 1;
                if (sm.g.P[mid] <= t) lo2 = mid; else hi2 = mid - 1;
            }
            sm.g.band[t] = (unsigned)lo2;
        }
        __syncthreads();

        const int c = tid & 63;
        const int s = tid >> 6;
        for (;;) {
            if (tid == 0) s_chunk = atomicAdd(&d_tick, 1u);
            __syncthreads();
            const unsigned t = s_chunk;
            if (t >= ntiles) break;
            const int b = (int)sm.g.band[t];
            const int ch = (int)sm.g.c0[b] + (int)(t - sm.g.P[b]);

            for (int i = tid; i < 3072; i += B) {
                const int a = i >> 9, e = i & 511;
                sm.g.tile[a * 512 + e] =
                    __ldcg(&((const u64*)(d_soa + a * N_PART))[ch * 512 + e]);
            }
            __syncthreads();

            const int m = 64 * b + c;
            const float cA = __ldcg(&d_sA[m]), cB = __ldcg(&d_sB[m]), cC = __ldcg(&d_sC[m]);
            const u64 A2c = pk(cA, cA), B2c = pk(cB, cB), C2c = pk(cC, cC);
            u64 ax = 0, ay = 0, aw = 0;
#pragma unroll 4
            for (int i = 0; i < 32; i += 2) {
                const int e = s * 32 + i;   // even -> 16B aligned
                ulonglong2 vx = *(const ulonglong2*)&sm.g.tile[e];
                ulonglong2 vy = *(const ulonglong2*)&sm.g.tile[512 + e];
                ulonglong2 vD = *(const ulonglong2*)&sm.g.tile[1024 + e];
                ulonglong2 vw = *(const ulonglong2*)&sm.g.tile[1536 + e];
                ulonglong2 wx = *(const ulonglong2*)&sm.g.tile[2048 + e];
                ulonglong2 wy = *(const ulonglong2*)&sm.g.tile[2560 + e];
                {
                    u64 u2 = fma2(A2c, vx.x, fma2(B2c, vy.x, add2(C2c, vD.x)));
                    float ua, ub;
                    upk(ua, ub, u2);
                    u64 e2 = pk(fast_exp2(ua), fast_exp2(ub));
                    ax = fma2(e2, wx.x, ax);
                    ay = fma2(e2, wy.x, ay);
                    aw = fma2(e2, vw.x, aw);
                }
                {
                    u64 u2 = fma2(A2c, vx.y, fma2(B2c, vy.y, add2(C2c, vD.y)));
                    float ua, ub;
                    upk(ua, ub, u2);
                    u64 e2 = pk(fast_exp2(ua), fast_exp2(ub));
                    ax = fma2(e2, wx.y, ax);
                    ay = fma2(e2, wy.y, ay);
                    aw = fma2(e2, vw.y, aw);
                }
            }
            float la, lb;
            upk(la, lb, ax); sm.g.red[(s * 64 + c) * 3 + 0] = la + lb;
            upk(la, lb, ay); sm.g.red[(s * 64 + c) * 3 + 1] = la + lb;
            upk(la, lb, aw); sm.g.red[(s * 64 + c) * 3 + 2] = la + lb;
            __syncthreads();
            if (tid < 192) {
                const int cc = tid & 63, comp = tid >> 6;
                float sum = 0.f;
#pragma unroll
                for (int s2 = 0; s2 < 16; ++s2) sum += sm.g.red[(s2 * 64 + cc) * 3 + comp];
                atomicAdd(&d_acc[comp * N_CENT + 64 * b + cc], sum);
            }
            __syncthreads();
        }
    }
    gbar(5);

    // ================= P7: finalize (sorted -> rank order) + rezero ==============
    if (gid < N_CENT) {
        unsigned r = __ldcg(&d_srank[gid]);
        float ax = __ldcg(&d_acc[gid]);
        float ay = __ldcg(&d_acc[N_CENT + gid]);
        float aw = __ldcg(&d_acc[2 * N_CENT + gid]);
        out[2 * r + 0] = ax / aw;
        out[2 * r + 1] = ay / aw;
        out[2 * N_CENT + r] = aw;
    }
    if (gid < NBINS) d_hist[gid] = 0u;
    if (gid >= NBINS && gid < NBINS + PBINS) d_phist[gid - NBINS] = 0u;
}

extern "C" void kernel_launch(void* const* d_in, const int* in_sizes, int n_in,
                              void* d_out, int out_size) {
    const float* x = (const float*)d_in[0];   // [32768, 2]
    const float* w = (const float*)d_in[1];   // [32768]
    float* out = (float*)d_out;               // 6144 floats: y (4096) then v (2048)

    k_all<<<G, B>>>(x, w, out);
}

// round 11
// speedup vs baseline: 2.6200x; 1.0599x over previous
#include <cuda_runtime.h>
#include <stdint.h>

#define N_PART 32768
#define N_CENT 2048
// SC = -log2(e)/tau, tau = 1e-3
#define SC_CONST (-1442.6950408889634f)
// cutoff: exp2(SC*d^2) < 2^-24 for d > RCUT
#define RCUT 0.1290f
#define G 148
#define B 1024
#define GA_N 64         // chain-A blocks (centroid path)
#define GB_N 84         // chain-B blocks (particle path)
#define NBINS 8192      // weight-bits histogram (top 13 bits)
#define PBINS 1024      // particle y bins
#define CBINS 256       // centroid y bins
#define PPB 222         // ceil(N_PART / G)

typedef unsigned long long u64;

__device__ float d_ccx[N_CENT], d_ccy[N_CENT];       // rank-ordered centroid coords
__device__ __align__(16) float d_sA[N_CENT + 4];     // y-sorted centroid constants (+pad)
__device__ __align__(16) float d_sB[N_CENT + 4];
__device__ __align__(16) float d_sC[N_CENT + 4];
__device__ float d_scy[N_CENT];                      // y-sorted centroid y
__device__ unsigned d_srank[N_CENT];                 // sorted index -> top-k rank
__device__ float d_spx[N_PART], d_spy[N_PART], d_spw[N_PART];   // y-sorted particles
__device__ __align__(256) float d_soa[3 * N_PART];   // sorted: x | y | pw
__device__ float d_acc[3 * N_CENT];                  // accX | accY | accW (sorted idx)
__device__ u64 d_cand[4096];
__device__ unsigned d_gcnt, d_tick;
__device__ unsigned d_hist[NBINS];
__device__ unsigned d_phist[PBINS];
__device__ unsigned d_chist[CBINS];
__device__ unsigned d_poff[PBINS];
__device__ unsigned d_coff[CBINS];
__device__ unsigned d_bar[8];                        // 0..2 A-bars, 3 B-bar, 4..6 full

union __align__(16) SmU {
    u64 keys[4096];                                  // 32 KB (rank phase)
    unsigned scan[1024];                             // scans
    struct {                                         // Z phase (~30 KB)
        u64 A2[1026], B2[1026], C2[1026];
        unsigned binC[257];
        float zp[256][4];
    } z;
    struct {                                         // gather phase (~42 KB)
        u64 tile[3072];                              // 1024 particles x 6 arrays
        float red[3072];                             // [16][64][3]
        unsigned pps[1025];
        unsigned c0[32];
        unsigned P[33];
        unsigned band[512];
    } g;
};

__device__ __forceinline__ float fast_exp2(float x) {
    float r;
    asm("ex2.approx.ftz.f32 %0, %1;" : "=f"(r) : "f"(x));
    return r;
}
__device__ __forceinline__ u64 pk(float lo, float hi) {
    u64 r; asm("mov.b64 %0, {%1, %2};" : "=l"(r) : "f"(lo), "f"(hi)); return r;
}
__device__ __forceinline__ void upk(float& lo, float& hi, u64 v) {
    asm("mov.b64 {%0, %1}, %2;" : "=f"(lo), "=f"(hi) : "l"(v));
}
__device__ __forceinline__ u64 fma2(u64 a, u64 b, u64 c) {
    u64 r; asm("fma.rn.f32x2 %0, %1, %2, %3;" : "=l"(r) : "l"(a), "l"(b), "l"(c)); return r;
}
__device__ __forceinline__ u64 add2(u64 a, u64 b) {
    u64 r; asm("add.rn.f32x2 %0, %1, %2;" : "=l"(r) : "l"(a), "l"(b)); return r;
}
__device__ __forceinline__ u64 mul2(u64 a, u64 b) {
    u64 r; asm("mul.rn.f32x2 %0, %1, %2;" : "=l"(r) : "l"(a), "l"(b)); return r;
}

__shared__ unsigned s_ws[32];

// Block-wide inclusive scan via warp shuffles: 3 barriers total.
__device__ __forceinline__ unsigned blockscan_incl(unsigned v) {
    const int lane = threadIdx.x & 31, wid = threadIdx.x >> 5;
    __syncthreads();                       // protect s_ws reuse
#pragma unroll
    for (int off = 1; off < 32; off <<= 1) {
        unsigned t = __shfl_up_sync(0xffffffffu, v, off);
        if (lane >= off) v += t;
    }
    if (lane == 31) s_ws[wid] = v;
    __syncthreads();
    if (wid == 0) {
        unsigned s = s_ws[lane];
#pragma unroll
        for (int off = 1; off < 32; off <<= 1) {
            unsigned t = __shfl_up_sync(0xffffffffu, s, off);
            if (lane >= off) s += t;
        }
        s_ws[lane] = s;
    }
    __syncthreads();
    if (wid > 0) v += s_ws[wid - 1];
    return v;
}

// Barrier over `count` blocks using slot `id`; monotonic, graph-replay safe.
__device__ __forceinline__ void gbarN(int id, unsigned count) {
    __syncthreads();
    if (threadIdx.x == 0) {
        __threadfence();
        unsigned my = atomicAdd(&d_bar[id], 1u) + 1u;
        unsigned tgt = ((my + count - 1u) / count) * count;
        while (*((volatile unsigned*)&d_bar[id]) < tgt) { }
        __threadfence();
    }
    __syncthreads();
}

__global__ void __launch_bounds__(B, 1) k_all(const float* __restrict__ x,
                                              const float* __restrict__ w,
                                              float* __restrict__ out) {
    __shared__ SmU sm;
    __shared__ unsigned s_tbin, s_chunk, s_total;

    const int tid = threadIdx.x;
    const int bid = blockIdx.x;
    const int gid = bid * B + tid;

    if (bid < GA_N) {
        // =================== CHAIN A: centroid path (blocks 0..63) ===============
        const int gidA = bid * B + tid;

        // ---- A1: w-hist + zero chain-A scratch ----
        unsigned wb = 0;
        if (gidA < N_PART) {
            wb = __float_as_uint(w[gidA]);
            atomicAdd(&d_hist[wb >> 19], 1u);
        }
        if (gidA < 3 * N_CENT) d_acc[gidA] = 0.0f;
        if (gidA >= 6144 && gidA < 6144 + CBINS) d_coff[gidA - 6144] = 0u;
        if (gidA >= 6400 && gidA < 6400 + CBINS) d_chist[gidA - 6400] = 0u;
        if (gidA == 6656) { d_gcnt = 0u; d_tick = 0u; }
        gbarN(0, GA_N);

        // ---- A2: threshold scan + compact ----
        {
            unsigned s = 0;
#pragma unroll
            for (int j = 0; j < NBINS / B; ++j) s += __ldcg(&d_hist[tid * (NBINS / B) + j]);
            unsigned Pin = blockscan_incl(s);
            if (tid == B - 1) s_total = Pin;
            __syncthreads();
            const unsigned total = s_total;
            if ((total - Pin + s) >= N_CENT && (total - Pin) < N_CENT) {
                unsigned cum = total - Pin;
                unsigned tb = (unsigned)(tid * (NBINS / B));
                for (int bin = tid * (NBINS / B) + NBINS / B - 1; bin >= tid * (NBINS / B); --bin) {
                    cum += __ldcg(&d_hist[bin]);
                    if (cum >= N_CENT) { tb = (unsigned)bin; break; }
                }
                s_tbin = tb;
            }
            __syncthreads();
        }
        const unsigned T = s_tbin << 19;
        if (gidA < N_PART && wb >= T) {
            unsigned p = atomicAdd(&d_gcnt, 1u);
            if (p < 4096u)
                d_cand[p] = ((u64)wb << 32) | (unsigned)(~gidA);
        }
        gbarN(1, GA_N);

        // ---- A3: exact rank -> rank-ordered coords + centroid y-hist ----
        {
            const unsigned C = min(__ldcg(&d_gcnt), 4096u);
            for (int j = tid; j < (int)C; j += B) sm.keys[j] = __ldcg(&d_cand[j]);
            __syncthreads();
            const int lane = tid & 31;
            const int ws = bid * (B / 32) + (tid >> 5);     // 2048 warp slots
            for (int c = ws; c < (int)C; c += GA_N * (B / 32)) {
                const u64 key = sm.keys[c];
                int r = 0;
                for (int j = lane; j < (int)C; j += 32) r += (sm.keys[j] > key);
                r = __reduce_add_sync(0xffffffffu, r);
                if (lane == 0 && r < N_CENT) {
                    unsigned idx = ~((unsigned)(key & 0xFFFFFFFFull));
                    float cx = x[2 * idx], cy = x[2 * idx + 1];
                    d_ccx[r] = cx;
                    d_ccy[r] = cy;
                    int cb = min(CBINS - 1, max(0, (int)(cy * (float)CBINS)));
                    atomicAdd(&d_chist[cb], 1u);
                }
            }
        }
        gbarN(2, GA_N);

        // ---- A4: centroid sort (bin prefix + scatter) + pad ----
        {
            unsigned h = (tid < CBINS) ? __ldcg(&d_chist[tid]) : 0u;
            unsigned excl = blockscan_incl(h) - h;
            if (tid < CBINS) sm.scan[tid] = excl;
            __syncthreads();
            if (gidA < N_CENT) {
                float cx = __ldcg(&d_ccx[gidA]), cy = __ldcg(&d_ccy[gidA]);
                int cb = min(CBINS - 1, max(0, (int)(cy * (float)CBINS)));
                unsigned pos = sm.scan[cb] + atomicAdd(&d_coff[cb], 1u);
                d_sA[pos] = SC_CONST * (-2.0f * cx);
                d_sB[pos] = SC_CONST * (-2.0f * cy);
                d_sC[pos] = SC_CONST * (cx * cx + cy * cy);
                d_scy[pos] = cy;
                d_srank[pos] = (unsigned)gidA;
            }
            if (gidA >= N_CENT && gidA < N_CENT + 4) {   // pad: contributes 0
                d_sA[gidA] = 0.0f; d_sB[gidA] = 0.0f; d_sC[gidA] = -100000.0f;
            }
        }
    } else {
        // =================== CHAIN B: particle path (blocks 64..147) =============
        const int gidB = (bid - GA_N) * B + tid;

        // ---- B1: y-hist + zero poff ----
        if (gidB < N_PART) {
            float py = ((const float2*)x)[gidB].y;
            int pb = min(PBINS - 1, max(0, (int)(py * (float)PBINS)));
            atomicAdd(&d_phist[pb], 1u);
        }
        if (gidB >= N_PART && gidB < N_PART + PBINS) d_poff[gidB - N_PART] = 0u;
        gbarN(3, GB_N);

        // ---- B2: particle y-bin exclusive prefix, then scatter ----
        {
            unsigned h = __ldcg(&d_phist[tid]);
            unsigned excl = blockscan_incl(h) - h;
            sm.scan[tid] = excl;
            __syncthreads();
            if (gidB < N_PART) {
                float2 xn = ((const float2*)x)[gidB];
                float wn = w[gidB];
                int pb = min(PBINS - 1, max(0, (int)(xn.y * (float)PBINS)));
                unsigned pos = sm.scan[pb] + atomicAdd(&d_poff[pb], 1u);
                d_spx[pos] = xn.x;
                d_spy[pos] = xn.y;
                d_spw[pos] = wn;
            }
        }
    }
    gbarN(4, G);   // ======== JOIN: both chains complete ========

    // ================= P5: Z pass, pruned + LDS.128 (even-pair groups) ============
    {
        for (int k = tid; k < 513; k += B) {
            float4 a = ((const float4*)d_sA)[k];
            float4 b = ((const float4*)d_sB)[k];
            float4 c = ((const float4*)d_sC)[k];
            ulonglong2 av; av.x = pk(a.x, a.y); av.y = pk(a.z, a.w);
            ulonglong2 bv; bv.x = pk(b.x, b.y); bv.y = pk(b.z, b.w);
            ulonglong2 cv; cv.x = pk(c.x, c.y); cv.y = pk(c.z, c.w);
            *(ulonglong2*)&sm.z.A2[2 * k] = av;
            *(ulonglong2*)&sm.z.B2[2 * k] = bv;
            *(ulonglong2*)&sm.z.C2[2 * k] = cv;
        }
        unsigned hC = (tid < CBINS) ? __ldcg(&d_chist[tid]) : 0u;
        unsigned exC = blockscan_incl(hC) - hC;
        if (tid < CBINS) sm.z.binC[tid] = exC;
        if (tid == 0) sm.z.binC[CBINS] = N_CENT;
        __syncthreads();

        const int local = tid & 255;
        const int q = tid >> 8;
        const int base = bid * PPB;
        const int cnt = min(PPB, N_PART - base);
        const bool act = (local < cnt);
        const int j = base + local;
        float px = 0.f, py = 0.f, pwin = 0.f;
        int lo = 0x7fffffff, hi = 0;
        if (act) {
            px = __ldcg(&d_spx[j]);
            py = __ldcg(&d_spy[j]);
            pwin = __ldcg(&d_spw[j]);
            int bl = min(CBINS - 1, max(0, (int)((py - RCUT) * (float)CBINS)));
            int bh = min(CBINS, max(1, (int)((py + RCUT) * (float)CBINS) + 1));
            lo = (int)sm.z.binC[bl];
            hi = (int)sm.z.binC[bh];
        }
        int lo_w = __reduce_min_sync(0xffffffffu, lo);
        int hi_w = __reduce_max_sync(0xffffffffu, hi);
        if (lo_w > hi_w) { lo_w = 0; hi_w = 0; }
        const int s_pi = lo_w >> 1;
        const int e_pi = (hi_w + 1) >> 1;
        const int s2 = s_pi >> 1;
        const int e2 = (e_pi + 1) >> 1;
        const int ng = e2 - s2;
        const int g0 = s2 + ((ng * q) >> 2);
        const int g1 = s2 + ((ng * (q + 1)) >> 2);

        const float D = SC_CONST * (px * px + py * py);
        const u64 xx0 = pk(px, px), xx1 = pk(py, py), DD = pk(D, D);
        u64 za = 0, zb = 0;
#pragma unroll 2
        for (int g = g0; g < g1; ++g) {
            ulonglong2 a = *(const ulonglong2*)&sm.z.A2[2 * g];
            ulonglong2 b = *(const ulonglong2*)&sm.z.B2[2 * g];
            ulonglong2 c = *(const ulonglong2*)&sm.z.C2[2 * g];
            u64 u2a = fma2(a.x, xx0, fma2(b.x, xx1, add2(c.x, DD)));
            u64 u2b = fma2(a.y, xx0, fma2(b.y, xx1, add2(c.y, DD)));
            float ua, ub, uc, ud;
            upk(ua, ub, u2a);
            upk(uc, ud, u2b);
            za = add2(za, pk(fast_exp2(ua), fast_exp2(ub)));
            zb = add2(zb, pk(fast_exp2(uc), fast_exp2(ud)));
        }
        if (act) {
            float s0, s1, s2f, s3;
            upk(s0, s1, za);
            upk(s2f, s3, zb);
            sm.z.zp[local][q] = (s0 + s1) + (s2f + s3);
        }
        __syncthreads();
        if (act && q == 0) {
            const float Z = sm.z.zp[local][0] + sm.z.zp[local][1]
                          + sm.z.zp[local][2] + sm.z.zp[local][3];
            const float pw = pwin / Z;
            d_soa[0 * N_PART + j] = px;
            d_soa[1 * N_PART + j] = py;
            d_soa[2 * N_PART + j] = pw;
        }
    }
    gbarN(5, G);

    // ================= P6: banded gather; 3-array staging, derived in-flight ======
    {
        unsigned h = __ldcg(&d_phist[tid]);
        unsigned excl = blockscan_incl(h) - h;
        sm.g.pps[tid] = excl;
        if (tid == 0) sm.g.pps[PBINS] = N_PART;
        __syncthreads();

        if (tid < 32) {
            int B0 = min(CBINS - 1, max(0, (int)(__ldcg(&d_scy[64 * tid]) * (float)CBINS)));
            int B1 = min(CBINS - 1, max(0, (int)(__ldcg(&d_scy[64 * tid + 63]) * (float)CBINS)));
            float yl = (float)B0 * (1.0f / CBINS) - RCUT;
            float yh = (float)(B1 + 1) * (1.0f / CBINS) + RCUT;
            int bl = min(PBINS - 1, max(0, (int)(yl * (float)PBINS)));
            int bh = min(PBINS, max(1, (int)(yh * (float)PBINS) + 1));
            unsigned jlo = sm.g.pps[bl], jhi = sm.g.pps[bh];
            sm.g.c0[tid] = jlo >> 10;
            sm.g.P[tid] = ((jhi + 1023u) >> 10) - (jlo >> 10);
        }
        __syncthreads();
        if (tid == 0) {
            unsigned run = 0;
            for (int b2 = 0; b2 < 32; ++b2) {
                unsigned t2 = sm.g.P[b2];
                sm.g.P[b2] = run;
                run += t2;
            }
            sm.g.P[32] = run;
        }
        __syncthreads();
        const unsigned ntiles = min(sm.g.P[32], 512u);
        for (unsigned t = tid; t < ntiles; t += B) {   // tile -> band map
            int lo2 = 0, hi2 = 31;
            while (lo2 < hi2) {
                int mid = (lo2 + hi2 + 1) >> 1;
                if (sm.g.P[mid] <= t) lo2 = mid; else hi2 = mid - 1;
            }
            sm.g.band[t] = (unsigned)lo2;
        }
        __syncthreads();

        const u64 SC2 = pk(SC_CONST, SC_CONST);
        const int c = tid & 63;
        const int s = tid >> 6;
        for (;;) {
            if (tid == 0) s_chunk = atomicAdd(&d_tick, 1u);
            __syncthreads();
            const unsigned t = s_chunk;
            if (t >= ntiles) break;
            const int b = (int)sm.g.band[t];
            const int ch = (int)sm.g.c0[b] + (int)(t - sm.g.P[b]);

            // stage: load (x,y,pw) pairs, derive (D, qx, qy) in-flight
            if (tid < 512) {
                const u64 px2 = __ldcg(&((const u64*)(d_soa + 0 * N_PART))[ch * 512 + tid]);
                const u64 py2 = __ldcg(&((const u64*)(d_soa + 1 * N_PART))[ch * 512 + tid]);
                const u64 pw2 = __ldcg(&((const u64*)(d_soa + 2 * N_PART))[ch * 512 + tid]);
                const u64 D2 = mul2(fma2(py2, py2, mul2(px2, px2)), SC2);
                sm.g.tile[tid]        = px2;
                sm.g.tile[512 + tid]  = py2;
                sm.g.tile[1024 + tid] = D2;
                sm.g.tile[1536 + tid] = pw2;
                sm.g.tile[2048 + tid] = mul2(pw2, px2);
                sm.g.tile[2560 + tid] = mul2(pw2, py2);
            }
            __syncthreads();

            const int m = 64 * b + c;
            const float cA = __ldcg(&d_sA[m]), cB = __ldcg(&d_sB[m]), cC = __ldcg(&d_sC[m]);
            const u64 A2c = pk(cA, cA), B2c = pk(cB, cB), C2c = pk(cC, cC);
            u64 ax = 0, ay = 0, aw = 0;
#pragma unroll 4
            for (int i = 0; i < 32; i += 2) {
                const int e = s * 32 + i;   // even -> 16B aligned
                ulonglong2 vx = *(const ulonglong2*)&sm.g.tile[e];
                ulonglong2 vy = *(const ulonglong2*)&sm.g.tile[512 + e];
                ulonglong2 vD = *(const ulonglong2*)&sm.g.tile[1024 + e];
                ulonglong2 vw = *(const ulonglong2*)&sm.g.tile[1536 + e];
                ulonglong2 wx = *(const ulonglong2*)&sm.g.tile[2048 + e];
                ulonglong2 wy = *(const ulonglong2*)&sm.g.tile[2560 + e];
                {
                    u64 u2 = fma2(A2c, vx.x, fma2(B2c, vy.x, add2(C2c, vD.x)));
                    float ua, ub;
                    upk(ua, ub, u2);
                    u64 e2 = pk(fast_exp2(ua), fast_exp2(ub));
                    ax = fma2(e2, wx.x, ax);
                    ay = fma2(e2, wy.x, ay);
                    aw = fma2(e2, vw.x, aw);
                }
                {
                    u64 u2 = fma2(A2c, vx.y, fma2(B2c, vy.y, add2(C2c, vD.y)));
                    float ua, ub;
                    upk(ua, ub, u2);
                    u64 e2 = pk(fast_exp2(ua), fast_exp2(ub));
                    ax = fma2(e2, wx.y, ax);
                    ay = fma2(e2, wy.y, ay);
                    aw = fma2(e2, vw.y, aw);
                }
            }
            float la, lb;
            upk(la, lb, ax); sm.g.red[(s * 64 + c) * 3 + 0] = la + lb;
            upk(la, lb, ay); sm.g.red[(s * 64 + c) * 3 + 1] = la + lb;
            upk(la, lb, aw); sm.g.red[(s * 64 + c) * 3 + 2] = la + lb;
            __syncthreads();
            if (tid < 192) {
                const int cc = tid & 63, comp = tid >> 6;
                float sum = 0.f;
#pragma unroll
                for (int s2 = 0; s2 < 16; ++s2) sum += sm.g.red[(s2 * 64 + cc) * 3 + comp];
                atomicAdd(&d_acc[comp * N_CENT + 64 * b + cc], sum);
            }
            __syncthreads();
        }
    }
    gbarN(6, G);

    // ================= P7: finalize (sorted -> rank order) + rezero ==============
    if (gid < N_CENT) {
        unsigned r = __ldcg(&d_srank[gid]);
        float ax = __ldcg(&d_acc[gid]);
        float ay = __ldcg(&d_acc[N_CENT + gid]);
        float aw = __ldcg(&d_acc[2 * N_CENT + gid]);
        out[2 * r + 0] = ax / aw;
        out[2 * r + 1] = ay / aw;
        out[2 * N_CENT + r] = aw;
    }
    if (gid < NBINS) d_hist[gid] = 0u;
    if (gid >= NBINS && gid < NBINS + PBINS) d_phist[gid - NBINS] = 0u;
}

extern "C" void kernel_launch(void* const* d_in, const int* in_sizes, int n_in,
                              void* d_out, int out_size) {
    const float* x = (const float*)d_in[0];   // [32768, 2]
    const float* w = (const float*)d_in[1];   // [32768]
    float* out = (float*)d_out;               // 6144 floats: y (4096) then v (2048)

    k_all<<<G, B>>>(x, w, out);
}

// round 12
// speedup vs baseline: 2.7234x; 1.0394x over previous
#include <cuda_runtime.h>
#include <stdint.h>

#define N_PART 32768
#define N_CENT 2048
// SC = -log2(e)/tau, tau = 1e-3
#define SC_CONST (-1442.6950408889634f)
// cutoff: exp2(SC*d^2) < 2^-18 for d > RCUT
#define RCUT 0.1117f
#define G 148
#define B 1024
#define GA_N 64         // chain-A blocks (centroid path)
#define GB_N 84         // chain-B blocks (particle path)
#define NBINS 8192      // weight-bits histogram (top 13 bits)
#define PBINS 1024      // particle y bins
#define CBINS 256       // centroid y bins
#define PPB 222         // ceil(N_PART / G)

typedef unsigned long long u64;

__device__ float d_ccx[N_CENT], d_ccy[N_CENT];       // rank-ordered centroid coords
__device__ __align__(16) float d_sA[N_CENT + 4];     // y-sorted centroid constants (+pad)
__device__ __align__(16) float d_sB[N_CENT + 4];
__device__ __align__(16) float d_sC[N_CENT + 4];
__device__ float d_scy[N_CENT];                      // y-sorted centroid y
__device__ unsigned d_srank[N_CENT];                 // sorted index -> top-k rank
__device__ float d_spx[N_PART], d_spy[N_PART], d_spw[N_PART];   // y-sorted particles
__device__ __align__(256) float d_soa[3 * N_PART];   // sorted: x | y | pw
__device__ float d_acc[3 * N_CENT];                  // accX | accY | accW (sorted idx)
__device__ u64 d_cand[4096];
__device__ unsigned d_gcnt;
__device__ unsigned d_hist[NBINS];
__device__ unsigned d_phist[PBINS];
__device__ unsigned d_chist[CBINS];
__device__ unsigned d_poff[PBINS];
__device__ unsigned d_coff[CBINS];
__device__ unsigned d_bar[8];                        // 0..2 A-bars, 3 B-bar, 4..6 full

union __align__(16) SmU {
    u64 keys[4096];                                  // 32 KB (rank phase)
    unsigned scan[1024];                             // scans
    struct {                                         // Z phase (~30 KB)
        u64 A2[1026], B2[1026], C2[1026];
        unsigned binC[257];
        float zp[256][4];
    } z;
    struct {                                         // gather phase (~42 KB)
        u64 tile[3072];                              // 1024 particles x 6 arrays
        float red[3072];                             // [16][64][3]
        unsigned pps[1025];
        unsigned c0[32];
        unsigned P[33];
        unsigned band[512];
    } g;
};

__device__ __forceinline__ float fast_exp2(float x) {
    float r;
    asm("ex2.approx.ftz.f32 %0, %1;" : "=f"(r) : "f"(x));
    return r;
}
__device__ __forceinline__ u64 pk(float lo, float hi) {
    u64 r; asm("mov.b64 %0, {%1, %2};" : "=l"(r) : "f"(lo), "f"(hi)); return r;
}
__device__ __forceinline__ void upk(float& lo, float& hi, u64 v) {
    asm("mov.b64 {%0, %1}, %2;" : "=f"(lo), "=f"(hi) : "l"(v));
}
__device__ __forceinline__ u64 fma2(u64 a, u64 b, u64 c) {
    u64 r; asm("fma.rn.f32x2 %0, %1, %2, %3;" : "=l"(r) : "l"(a), "l"(b), "l"(c)); return r;
}
__device__ __forceinline__ u64 add2(u64 a, u64 b) {
    u64 r; asm("add.rn.f32x2 %0, %1, %2;" : "=l"(r) : "l"(a), "l"(b)); return r;
}
__device__ __forceinline__ u64 mul2(u64 a, u64 b) {
    u64 r; asm("mul.rn.f32x2 %0, %1, %2;" : "=l"(r) : "l"(a), "l"(b)); return r;
}

__shared__ unsigned s_ws[32];

// Block-wide inclusive scan via warp shuffles: 3 barriers total.
__device__ __forceinline__ unsigned blockscan_incl(unsigned v) {
    const int lane = threadIdx.x & 31, wid = threadIdx.x >> 5;
    __syncthreads();                       // protect s_ws reuse
#pragma unroll
    for (int off = 1; off < 32; off <<= 1) {
        unsigned t = __shfl_up_sync(0xffffffffu, v, off);
        if (lane >= off) v += t;
    }
    if (lane == 31) s_ws[wid] = v;
    __syncthreads();
    if (wid == 0) {
        unsigned s = s_ws[lane];
#pragma unroll
        for (int off = 1; off < 32; off <<= 1) {
            unsigned t = __shfl_up_sync(0xffffffffu, s, off);
            if (lane >= off) s += t;
        }
        s_ws[lane] = s;
    }
    __syncthreads();
    if (wid > 0) v += s_ws[wid - 1];
    return v;
}

// Barrier over `count` blocks using slot `id`; monotonic, graph-replay safe.
__device__ __forceinline__ void gbarN(int id, unsigned count) {
    __syncthreads();
    if (threadIdx.x == 0) {
        __threadfence();
        unsigned my = atomicAdd(&d_bar[id], 1u) + 1u;
        unsigned tgt = ((my + count - 1u) / count) * count;
        while (*((volatile unsigned*)&d_bar[id]) < tgt) { }
        __threadfence();
    }
    __syncthreads();
}

__global__ void __launch_bounds__(B, 1) k_all(const float* __restrict__ x,
                                              const float* __restrict__ w,
                                              float* __restrict__ out) {
    __shared__ SmU sm;
    __shared__ unsigned s_tbin, s_total;

    const int tid = threadIdx.x;
    const int bid = blockIdx.x;
    const int gid = bid * B + tid;

    if (bid < GA_N) {
        // =================== CHAIN A: centroid path (blocks 0..63) ===============
        const int gidA = bid * B + tid;

        // ---- A1: w-hist + zero chain-A scratch ----
        unsigned wb = 0;
        if (gidA < N_PART) {
            wb = __float_as_uint(w[gidA]);
            atomicAdd(&d_hist[wb >> 19], 1u);
        }
        if (gidA < 3 * N_CENT) d_acc[gidA] = 0.0f;
        if (gidA >= 6144 && gidA < 6144 + CBINS) d_coff[gidA - 6144] = 0u;
        if (gidA >= 6400 && gidA < 6400 + CBINS) d_chist[gidA - 6400] = 0u;
        if (gidA == 6656) d_gcnt = 0u;
        gbarN(0, GA_N);

        // ---- A2: threshold scan + compact ----
        {
            unsigned s = 0;
#pragma unroll
            for (int j = 0; j < NBINS / B; ++j) s += __ldcg(&d_hist[tid * (NBINS / B) + j]);
            unsigned Pin = blockscan_incl(s);
            if (tid == B - 1) s_total = Pin;
            __syncthreads();
            const unsigned total = s_total;
            if ((total - Pin + s) >= N_CENT && (total - Pin) < N_CENT) {
                unsigned cum = total - Pin;
                unsigned tb = (unsigned)(tid * (NBINS / B));
                for (int bin = tid * (NBINS / B) + NBINS / B - 1; bin >= tid * (NBINS / B); --bin) {
                    cum += __ldcg(&d_hist[bin]);
                    if (cum >= N_CENT) { tb = (unsigned)bin; break; }
                }
                s_tbin = tb;
            }
            __syncthreads();
        }
        const unsigned T = s_tbin << 19;
        if (gidA < N_PART && wb >= T) {
            unsigned p = atomicAdd(&d_gcnt, 1u);
            if (p < 4096u)
                d_cand[p] = ((u64)wb << 32) | (unsigned)(~gidA);
        }
        gbarN(1, GA_N);

        // ---- A3: exact rank -> rank-ordered coords + centroid y-hist ----
        {
            const unsigned C = min(__ldcg(&d_gcnt), 4096u);
            for (int j = tid; j < (int)C; j += B) sm.keys[j] = __ldcg(&d_cand[j]);
            __syncthreads();
            const int lane = tid & 31;
            const int ws = bid * (B / 32) + (tid >> 5);     // 2048 warp slots
            for (int c = ws; c < (int)C; c += GA_N * (B / 32)) {
                const u64 key = sm.keys[c];
                int r = 0;
                for (int j = lane; j < (int)C; j += 32) r += (sm.keys[j] > key);
                r = __reduce_add_sync(0xffffffffu, r);
                if (lane == 0 && r < N_CENT) {
                    unsigned idx = ~((unsigned)(key & 0xFFFFFFFFull));
                    float cx = x[2 * idx], cy = x[2 * idx + 1];
                    d_ccx[r] = cx;
                    d_ccy[r] = cy;
                    int cb = min(CBINS - 1, max(0, (int)(cy * (float)CBINS)));
                    atomicAdd(&d_chist[cb], 1u);
                }
            }
        }
        gbarN(2, GA_N);

        // ---- A4: centroid sort (bin prefix + scatter) + pad ----
        {
            unsigned h = (tid < CBINS) ? __ldcg(&d_chist[tid]) : 0u;
            unsigned excl = blockscan_incl(h) - h;
            if (tid < CBINS) sm.scan[tid] = excl;
            __syncthreads();
            if (gidA < N_CENT) {
                float cx = __ldcg(&d_ccx[gidA]), cy = __ldcg(&d_ccy[gidA]);
                int cb = min(CBINS - 1, max(0, (int)(cy * (float)CBINS)));
                unsigned pos = sm.scan[cb] + atomicAdd(&d_coff[cb], 1u);
                d_sA[pos] = SC_CONST * (-2.0f * cx);
                d_sB[pos] = SC_CONST * (-2.0f * cy);
                d_sC[pos] = SC_CONST * (cx * cx + cy * cy);
                d_scy[pos] = cy;
                d_srank[pos] = (unsigned)gidA;
            }
            if (gidA >= N_CENT && gidA < N_CENT + 4) {   // pad: contributes 0
                d_sA[gidA] = 0.0f; d_sB[gidA] = 0.0f; d_sC[gidA] = -100000.0f;
            }
        }
    } else {
        // =================== CHAIN B: particle path (blocks 64..147) =============
        const int gidB = (bid - GA_N) * B + tid;

        // ---- B1: y-hist + zero poff ----
        if (gidB < N_PART) {
            float py = ((const float2*)x)[gidB].y;
            int pb = min(PBINS - 1, max(0, (int)(py * (float)PBINS)));
            atomicAdd(&d_phist[pb], 1u);
        }
        if (gidB >= N_PART && gidB < N_PART + PBINS) d_poff[gidB - N_PART] = 0u;
        gbarN(3, GB_N);

        // ---- B2: particle y-bin exclusive prefix, then scatter ----
        {
            unsigned h = __ldcg(&d_phist[tid]);
            unsigned excl = blockscan_incl(h) - h;
            sm.scan[tid] = excl;
            __syncthreads();
            if (gidB < N_PART) {
                float2 xn = ((const float2*)x)[gidB];
                float wn = w[gidB];
                int pb = min(PBINS - 1, max(0, (int)(xn.y * (float)PBINS)));
                unsigned pos = sm.scan[pb] + atomicAdd(&d_poff[pb], 1u);
                d_spx[pos] = xn.x;
                d_spy[pos] = xn.y;
                d_spw[pos] = wn;
            }
        }
    }
    gbarN(4, G);   // ======== JOIN: both chains complete ========

    // ================= P5: Z pass, pruned + LDS.128 (even-pair groups) ============
    {
        for (int k = tid; k < 513; k += B) {
            float4 a = ((const float4*)d_sA)[k];
            float4 b = ((const float4*)d_sB)[k];
            float4 c = ((const float4*)d_sC)[k];
            ulonglong2 av; av.x = pk(a.x, a.y); av.y = pk(a.z, a.w);
            ulonglong2 bv; bv.x = pk(b.x, b.y); bv.y = pk(b.z, b.w);
            ulonglong2 cv; cv.x = pk(c.x, c.y); cv.y = pk(c.z, c.w);
            *(ulonglong2*)&sm.z.A2[2 * k] = av;
            *(ulonglong2*)&sm.z.B2[2 * k] = bv;
            *(ulonglong2*)&sm.z.C2[2 * k] = cv;
        }
        unsigned hC = (tid < CBINS) ? __ldcg(&d_chist[tid]) : 0u;
        unsigned exC = blockscan_incl(hC) - hC;
        if (tid < CBINS) sm.z.binC[tid] = exC;
        if (tid == 0) sm.z.binC[CBINS] = N_CENT;
        __syncthreads();

        const int local = tid & 255;
        const int q = tid >> 8;
        const int base = bid * PPB;
        const int cnt = min(PPB, N_PART - base);
        const bool act = (local < cnt);
        const int j = base + local;
        float px = 0.f, py = 0.f, pwin = 0.f;
        int lo = 0x7fffffff, hi = 0;
        if (act) {
            px = __ldcg(&d_spx[j]);
            py = __ldcg(&d_spy[j]);
            pwin = __ldcg(&d_spw[j]);
            int bl = min(CBINS - 1, max(0, (int)((py - RCUT) * (float)CBINS)));
            int bh = min(CBINS, max(1, (int)((py + RCUT) * (float)CBINS) + 1));
            lo = (int)sm.z.binC[bl];
            hi = (int)sm.z.binC[bh];
        }
        int lo_w = __reduce_min_sync(0xffffffffu, lo);
        int hi_w = __reduce_max_sync(0xffffffffu, hi);
        if (lo_w > hi_w) { lo_w = 0; hi_w = 0; }
        const int s_pi = lo_w >> 1;
        const int e_pi = (hi_w + 1) >> 1;
        const int s2 = s_pi >> 1;
        const int e2 = (e_pi + 1) >> 1;
        const int ng = e2 - s2;
        const int g0 = s2 + ((ng * q) >> 2);
        const int g1 = s2 + ((ng * (q + 1)) >> 2);

        const float D = SC_CONST * (px * px + py * py);
        const u64 xx0 = pk(px, px), xx1 = pk(py, py), DD = pk(D, D);
        u64 za = 0, zb = 0;
#pragma unroll 2
        for (int g = g0; g < g1; ++g) {
            ulonglong2 a = *(const ulonglong2*)&sm.z.A2[2 * g];
            ulonglong2 b = *(const ulonglong2*)&sm.z.B2[2 * g];
            ulonglong2 c = *(const ulonglong2*)&sm.z.C2[2 * g];
            u64 u2a = fma2(a.x, xx0, fma2(b.x, xx1, add2(c.x, DD)));
            u64 u2b = fma2(a.y, xx0, fma2(b.y, xx1, add2(c.y, DD)));
            float ua, ub, uc, ud;
            upk(ua, ub, u2a);
            upk(uc, ud, u2b);
            za = add2(za, pk(fast_exp2(ua), fast_exp2(ub)));
            zb = add2(zb, pk(fast_exp2(uc), fast_exp2(ud)));
        }
        if (act) {
            float s0, s1, s2f, s3;
            upk(s0, s1, za);
            upk(s2f, s3, zb);
            sm.z.zp[local][q] = (s0 + s1) + (s2f + s3);
        }
        __syncthreads();
        if (act && q == 0) {
            const float Z = sm.z.zp[local][0] + sm.z.zp[local][1]
                          + sm.z.zp[local][2] + sm.z.zp[local][3];
            const float pw = pwin / Z;
            d_soa[0 * N_PART + j] = px;
            d_soa[1 * N_PART + j] = py;
            d_soa[2 * N_PART + j] = pw;
        }
    }
    gbarN(5, G);

    // ================= P6: banded gather; static tile ranges, reg accumulators ====
    {
        unsigned h = __ldcg(&d_phist[tid]);
        unsigned excl = blockscan_incl(h) - h;
        sm.g.pps[tid] = excl;
        if (tid == 0) sm.g.pps[PBINS] = N_PART;
        __syncthreads();

        if (tid < 32) {
            int B0 = min(CBINS - 1, max(0, (int)(__ldcg(&d_scy[64 * tid]) * (float)CBINS)));
            int B1 = min(CBINS - 1, max(0, (int)(__ldcg(&d_scy[64 * tid + 63]) * (float)CBINS)));
            float yl = (float)B0 * (1.0f / CBINS) - RCUT;
            float yh = (float)(B1 + 1) * (1.0f / CBINS) + RCUT;
            int bl = min(PBINS - 1, max(0, (int)(yl * (float)PBINS)));
            int bh = min(PBINS, max(1, (int)(yh * (float)PBINS) + 1));
            unsigned jlo = sm.g.pps[bl], jhi = sm.g.pps[bh];
            sm.g.c0[tid] = jlo >> 10;
            sm.g.P[tid] = ((jhi + 1023u) >> 10) - (jlo >> 10);
        }
        __syncthreads();
        if (tid == 0) {
            unsigned run = 0;
            for (int b2 = 0; b2 < 32; ++b2) {
                unsigned t2 = sm.g.P[b2];
                sm.g.P[b2] = run;
                run += t2;
            }
            sm.g.P[32] = run;
        }
        __syncthreads();
        const unsigned ntiles = min(sm.g.P[32], 512u);
        for (unsigned t = tid; t < ntiles; t += B) {   // tile -> band map
            int lo2 = 0, hi2 = 31;
            while (lo2 < hi2) {
                int mid = (lo2 + hi2 + 1) >> 1;
                if (sm.g.P[mid] <= t) lo2 = mid; else hi2 = mid - 1;
            }
            sm.g.band[t] = (unsigned)lo2;
        }
        __syncthreads();

        const u64 SC2 = pk(SC_CONST, SC_CONST);
        const int c = tid & 63;
        const int s = tid >> 6;
        const unsigned t0 = (ntiles * (unsigned)bid) / (unsigned)G;
        const unsigned t1 = (ntiles * (unsigned)(bid + 1)) / (unsigned)G;

        u64 ax = 0, ay = 0, aw = 0;
        int curb = -1;
        float cA = 0.f, cB = 0.f, cC = 0.f;

        for (unsigned t = t0; t < t1; ++t) {
            const int b = (int)sm.g.band[t];
            if (b != curb) {
                if (curb >= 0) {   // flush accumulated band (block-uniform path)
                    float la, lb;
                    upk(la, lb, ax); sm.g.red[(s * 64 + c) * 3 + 0] = la + lb;
                    upk(la, lb, ay); sm.g.red[(s * 64 + c) * 3 + 1] = la + lb;
                    upk(la, lb, aw); sm.g.red[(s * 64 + c) * 3 + 2] = la + lb;
                    __syncthreads();
                    if (tid < 192) {
                        const int cc = tid & 63, comp = tid >> 6;
                        float sum = 0.f;
#pragma unroll
                        for (int s2 = 0; s2 < 16; ++s2)
                            sum += sm.g.red[(s2 * 64 + cc) * 3 + comp];
                        atomicAdd(&d_acc[comp * N_CENT + 64 * curb + cc], sum);
                    }
                    ax = 0; ay = 0; aw = 0;
                }
                curb = b;
                const int m = 64 * b + c;
                cA = __ldcg(&d_sA[m]); cB = __ldcg(&d_sB[m]); cC = __ldcg(&d_sC[m]);
            }
            const int ch = (int)sm.g.c0[b] + (int)(t - sm.g.P[b]);

            __syncthreads();   // tile (and red) reuse guard
            if (tid < 512) {
                const u64 px2 = __ldcg(&((const u64*)(d_soa + 0 * N_PART))[ch * 512 + tid]);
                const u64 py2 = __ldcg(&((const u64*)(d_soa + 1 * N_PART))[ch * 512 + tid]);
                const u64 pw2 = __ldcg(&((const u64*)(d_soa + 2 * N_PART))[ch * 512 + tid]);
                const u64 D2 = mul2(fma2(py2, py2, mul2(px2, px2)), SC2);
                sm.g.tile[tid]        = px2;
                sm.g.tile[512 + tid]  = py2;
                sm.g.tile[1024 + tid] = D2;
                sm.g.tile[1536 + tid] = pw2;
                sm.g.tile[2048 + tid] = mul2(pw2, px2);
                sm.g.tile[2560 + tid] = mul2(pw2, py2);
            }
            __syncthreads();

            const u64 A2c = pk(cA, cA), B2c = pk(cB, cB), C2c = pk(cC, cC);
#pragma unroll 4
            for (int i = 0; i < 32; i += 2) {
                const int e = s * 32 + i;   // even -> 16B aligned
                ulonglong2 vx = *(const ulonglong2*)&sm.g.tile[e];
                ulonglong2 vy = *(const ulonglong2*)&sm.g.tile[512 + e];
                ulonglong2 vD = *(const ulonglong2*)&sm.g.tile[1024 + e];
                ulonglong2 vw = *(const ulonglong2*)&sm.g.tile[1536 + e];
                ulonglong2 wx = *(const ulonglong2*)&sm.g.tile[2048 + e];
                ulonglong2 wy = *(const ulonglong2*)&sm.g.tile[2560 + e];
                {
                    u64 u2 = fma2(A2c, vx.x, fma2(B2c, vy.x, add2(C2c, vD.x)));
                    float ua, ub;
                    upk(ua, ub, u2);
                    u64 e2 = pk(fast_exp2(ua), fast_exp2(ub));
                    ax = fma2(e2, wx.x, ax);
                    ay = fma2(e2, wy.x, ay);
                    aw = fma2(e2, vw.x, aw);
                }
                {
                    u64 u2 = fma2(A2c, vx.y, fma2(B2c, vy.y, add2(C2c, vD.y)));
                    float ua, ub;
                    upk(ua, ub, u2);
                    u64 e2 = pk(fast_exp2(ua), fast_exp2(ub));
                    ax = fma2(e2, wx.y, ax);
                    ay = fma2(e2, wy.y, ay);
                    aw = fma2(e2, vw.y, aw);
                }
            }
        }
        if (curb >= 0) {   // final flush
            float la, lb;
            upk(la, lb, ax); sm.g.red[(s * 64 + c) * 3 + 0] = la + lb;
            upk(la, lb, ay); sm.g.red[(s * 64 + c) * 3 + 1] = la + lb;
            upk(la, lb, aw); sm.g.red[(s * 64 + c) * 3 + 2] = la + lb;
            __syncthreads();
            if (tid < 192) {
                const int cc = tid & 63, comp = tid >> 6;
                float sum = 0.f;
#pragma unroll
                for (int s2 = 0; s2 < 16; ++s2)
                    sum += sm.g.red[(s2 * 64 + cc) * 3 + comp];
                atomicAdd(&d_acc[comp * N_CENT + 64 * curb + cc], sum);
            }
        }
    }
    gbarN(6, G);

    // ================= P7: finalize (sorted -> rank order) + rezero ==============
    if (gid < N_CENT) {
        unsigned r = __ldcg(&d_srank[gid]);
        float ax = __ldcg(&d_acc[gid]);
        float ay = __ldcg(&d_acc[N_CENT + gid]);
        float aw = __ldcg(&d_acc[2 * N_CENT + gid]);
        out[2 * r + 0] = ax / aw;
        out[2 * r + 1] = ay / aw;
        out[2 * N_CENT + r] = aw;
    }
    if (gid < NBINS) d_hist[gid] = 0u;
    if (gid >= NBINS && gid < NBINS + PBINS) d_phist[gid - NBINS] = 0u;
}

extern "C" void kernel_launch(void* const* d_in, const int* in_sizes, int n_in,
                              void* d_out, int out_size) {
    const float* x = (const float*)d_in[0];   // [32768, 2]
    const float* w = (const float*)d_in[1];   // [32768]
    float* out = (float*)d_out;               // 6144 floats: y (4096) then v (2048)

    k_all<<<G, B>>>(x, w, out);
}

// round 13
// speedup vs baseline: 2.9704x; 1.0907x over previous
#include <cuda_runtime.h>
#include <stdint.h>

#define N_PART 32768
#define N_CENT 2048
// SC = -log2(e)/tau, tau = 1e-3
#define SC_CONST (-1442.6950408889634f)
// cutoff: exp2(SC*d^2) < 2^-18 for d > RCUT
#define RCUT 0.1117f
#define G 148
#define B 1024
#define GA_N 64         // chain-A blocks (centroid path)
#define GB_N 84         // chain-B blocks (particle path)
#define NBINS 8192      // weight-bits histogram (top 13 bits)
#define PBINS 1024      // particle y bins
#define CBINS 256       // centroid y bins
#define NGRAN 1024      // 32-particle granules

typedef unsigned long long u64;

__device__ float d_ccx[N_CENT], d_ccy[N_CENT];       // rank-ordered centroid coords
__device__ __align__(16) float d_sA[N_CENT + 4];     // y-sorted centroid constants (+pad)
__device__ __align__(16) float d_sB[N_CENT + 4];
__device__ __align__(16) float d_sC[N_CENT + 4];
__device__ float d_scy[N_CENT];                      // y-sorted centroid y
__device__ unsigned d_srank[N_CENT];                 // sorted index -> top-k rank
__device__ float d_spx[N_PART], d_spy[N_PART], d_spw[N_PART];   // y-sorted particles
__device__ __align__(256) float d_soa[3 * N_PART];   // sorted: x | y | pw
__device__ float d_acc[3 * N_CENT];                  // accX | accY | accW (sorted idx)
__device__ u64 d_cand[4096];
__device__ unsigned d_gcnt;
__device__ unsigned d_hist[NBINS];
__device__ unsigned d_phist[PBINS];
__device__ unsigned d_chist[CBINS];
__device__ unsigned d_poff[PBINS];
__device__ unsigned d_coff[CBINS];
__device__ unsigned d_binCg[CBINS];                  // stashed centroid-bin excl scan
__device__ unsigned d_ppsg[PBINS];                   // stashed particle-bin excl scan
__device__ unsigned d_bar[8];                        // 0..2 A-bars, 3 B-bar, 4..6 full

union __align__(16) SmU {
    u64 keys[4096];                                  // 32 KB (rank phase)
    unsigned scan[1024];                             // scans
    struct {                                         // Z phase (~30 KB)
        u64 A2[1026], B2[1026], C2[1026];
        unsigned binC[257];
        float zp[256][4];
    } z;
    struct {                                         // gather phase (~42 KB)
        u64 tile[3072];                              // 1024 particles x 6 arrays
        float red[3072];                             // [16][64][3]
        unsigned pps[1025];
        unsigned c0[32];
        unsigned P[33];
        unsigned band[512];
    } g;
};

__device__ __forceinline__ float fast_exp2(float x) {
    float r;
    asm("ex2.approx.ftz.f32 %0, %1;" : "=f"(r) : "f"(x));
    return r;
}
__device__ __forceinline__ u64 pk(float lo, float hi) {
    u64 r; asm("mov.b64 %0, {%1, %2};" : "=l"(r) : "f"(lo), "f"(hi)); return r;
}
__device__ __forceinline__ void upk(float& lo, float& hi, u64 v) {
    asm("mov.b64 {%0, %1}, %2;" : "=f"(lo), "=f"(hi) : "l"(v));
}
__device__ __forceinline__ u64 fma2(u64 a, u64 b, u64 c) {
    u64 r; asm("fma.rn.f32x2 %0, %1, %2, %3;" : "=l"(r) : "l"(a), "l"(b), "l"(c)); return r;
}
__device__ __forceinline__ u64 add2(u64 a, u64 b) {
    u64 r; asm("add.rn.f32x2 %0, %1, %2;" : "=l"(r) : "l"(a), "l"(b)); return r;
}
__device__ __forceinline__ u64 mul2(u64 a, u64 b) {
    u64 r; asm("mul.rn.f32x2 %0, %1, %2;" : "=l"(r) : "l"(a), "l"(b)); return r;
}

__shared__ unsigned s_ws[32];

// Block-wide inclusive scan via warp shuffles: 3 barriers total.
__device__ __forceinline__ unsigned blockscan_incl(unsigned v) {
    const int lane = threadIdx.x & 31, wid = threadIdx.x >> 5;
    __syncthreads();                       // protect s_ws reuse
#pragma unroll
    for (int off = 1; off < 32; off <<= 1) {
        unsigned t = __shfl_up_sync(0xffffffffu, v, off);
        if (lane >= off) v += t;
    }
    if (lane == 31) s_ws[wid] = v;
    __syncthreads();
    if (wid == 0) {
        unsigned s = s_ws[lane];
#pragma unroll
        for (int off = 1; off < 32; off <<= 1) {
            unsigned t = __shfl_up_sync(0xffffffffu, s, off);
            if (lane >= off) s += t;
        }
        s_ws[lane] = s;
    }
    __syncthreads();
    if (wid > 0) v += s_ws[wid - 1];
    return v;
}

// Barrier over `count` blocks using slot `id`; monotonic, graph-replay safe.
__device__ __forceinline__ void gbarN(int id, unsigned count) {
    __syncthreads();
    if (threadIdx.x == 0) {
        __threadfence();
        unsigned my = atomicAdd(&d_bar[id], 1u) + 1u;
        unsigned tgt = ((my + count - 1u) / count) * count;
        while (*((volatile unsigned*)&d_bar[id]) < tgt) { }
        __threadfence();
    }
    __syncthreads();
}

__global__ void __launch_bounds__(B, 1) k_all(const float* __restrict__ x,
                                              const float* __restrict__ w,
                                              float* __restrict__ out) {
    __shared__ SmU sm;
    __shared__ unsigned s_tbin, s_total;

    const int tid = threadIdx.x;
    const int bid = blockIdx.x;
    const int gid = bid * B + tid;

    if (bid < GA_N) {
        // =================== CHAIN A: centroid path (blocks 0..63) ===============
        const int gidA = bid * B + tid;

        // ---- A1: w-hist + zero chain-A scratch ----
        unsigned wb = 0;
        if (gidA < N_PART) {
            wb = __float_as_uint(w[gidA]);
            atomicAdd(&d_hist[wb >> 19], 1u);
        }
        if (gidA < 3 * N_CENT) d_acc[gidA] = 0.0f;
        if (gidA >= 6144 && gidA < 6144 + CBINS) d_coff[gidA - 6144] = 0u;
        if (gidA >= 6400 && gidA < 6400 + CBINS) d_chist[gidA - 6400] = 0u;
        if (gidA == 6656) d_gcnt = 0u;
        gbarN(0, GA_N);

        // ---- A2: threshold scan + compact ----
        {
            unsigned s = 0;
#pragma unroll
            for (int j = 0; j < NBINS / B; ++j) s += __ldcg(&d_hist[tid * (NBINS / B) + j]);
            unsigned Pin = blockscan_incl(s);
            if (tid == B - 1) s_total = Pin;
            __syncthreads();
            const unsigned total = s_total;
            if ((total - Pin + s) >= N_CENT && (total - Pin) < N_CENT) {
                unsigned cum = total - Pin;
                unsigned tb = (unsigned)(tid * (NBINS / B));
                for (int bin = tid * (NBINS / B) + NBINS / B - 1; bin >= tid * (NBINS / B); --bin) {
                    cum += __ldcg(&d_hist[bin]);
                    if (cum >= N_CENT) { tb = (unsigned)bin; break; }
                }
                s_tbin = tb;
            }
            __syncthreads();
        }
        const unsigned T = s_tbin << 19;
        if (gidA < N_PART && wb >= T) {
            unsigned p = atomicAdd(&d_gcnt, 1u);
            if (p < 4096u)
                d_cand[p] = ((u64)wb << 32) | (unsigned)(~gidA);
        }
        gbarN(1, GA_N);

        // ---- A3: exact rank -> rank-ordered coords + centroid y-hist ----
        {
            const unsigned C = min(__ldcg(&d_gcnt), 4096u);
            for (int j = tid; j < (int)C; j += B) sm.keys[j] = __ldcg(&d_cand[j]);
            __syncthreads();
            const int lane = tid & 31;
            const int ws = bid * (B / 32) + (tid >> 5);     // 2048 warp slots
            for (int c = ws; c < (int)C; c += GA_N * (B / 32)) {
                const u64 key = sm.keys[c];
                int r = 0;
                for (int j = lane; j < (int)C; j += 32) r += (sm.keys[j] > key);
                r = __reduce_add_sync(0xffffffffu, r);
                if (lane == 0 && r < N_CENT) {
                    unsigned idx = ~((unsigned)(key & 0xFFFFFFFFull));
                    float cx = x[2 * idx], cy = x[2 * idx + 1];
                    d_ccx[r] = cx;
                    d_ccy[r] = cy;
                    int cb = min(CBINS - 1, max(0, (int)(cy * (float)CBINS)));
                    atomicAdd(&d_chist[cb], 1u);
                }
            }
        }
        gbarN(2, GA_N);

        // ---- A4: centroid sort (bin prefix + scatter) + pad + scan stash ----
        {
            unsigned h = (tid < CBINS) ? __ldcg(&d_chist[tid]) : 0u;
            unsigned excl = blockscan_incl(h) - h;
            if (tid < CBINS) sm.scan[tid] = excl;
            if (bid == 0 && tid < CBINS) d_binCg[tid] = excl;   // stash for P5
            __syncthreads();
            if (gidA < N_CENT) {
                float cx = __ldcg(&d_ccx[gidA]), cy = __ldcg(&d_ccy[gidA]);
                int cb = min(CBINS - 1, max(0, (int)(cy * (float)CBINS)));
                unsigned pos = sm.scan[cb] + atomicAdd(&d_coff[cb], 1u);
                d_sA[pos] = SC_CONST * (-2.0f * cx);
                d_sB[pos] = SC_CONST * (-2.0f * cy);
                d_sC[pos] = SC_CONST * (cx * cx + cy * cy);
                d_scy[pos] = cy;
                d_srank[pos] = (unsigned)gidA;
            }
            if (gidA >= N_CENT && gidA < N_CENT + 4) {   // pad: contributes 0
                d_sA[gidA] = 0.0f; d_sB[gidA] = 0.0f; d_sC[gidA] = -100000.0f;
            }
        }
    } else {
        // =================== CHAIN B: particle path (blocks 64..147) =============
        const int gidB = (bid - GA_N) * B + tid;

        // ---- B1: y-hist + zero poff ----
        if (gidB < N_PART) {
            float py = ((const float2*)x)[gidB].y;
            int pb = min(PBINS - 1, max(0, (int)(py * (float)PBINS)));
            atomicAdd(&d_phist[pb], 1u);
        }
        if (gidB >= N_PART && gidB < N_PART + PBINS) d_poff[gidB - N_PART] = 0u;
        gbarN(3, GB_N);

        // ---- B2: particle y-bin exclusive prefix, scatter, scan stash ----
        {
            unsigned h = __ldcg(&d_phist[tid]);
            unsigned excl = blockscan_incl(h) - h;
            sm.scan[tid] = excl;
            if (bid == GA_N) d_ppsg[tid] = excl;               // stash for P6
            __syncthreads();
            if (gidB < N_PART) {
                float2 xn = ((const float2*)x)[gidB];
                float wn = w[gidB];
                int pb = min(PBINS - 1, max(0, (int)(xn.y * (float)PBINS)));
                unsigned pos = sm.scan[pb] + atomicAdd(&d_poff[pb], 1u);
                d_spx[pos] = xn.x;
                d_spy[pos] = xn.y;
                d_spw[pos] = wn;
            }
        }
    }
    gbarN(4, G);   // ======== JOIN: both chains complete ========

    // ================= P5: Z pass, granule round-robin + LDS.128 =================
    {
        for (int k = tid; k < 513; k += B) {
            float4 a = ((const float4*)d_sA)[k];
            float4 b = ((const float4*)d_sB)[k];
            float4 c = ((const float4*)d_sC)[k];
            ulonglong2 av; av.x = pk(a.x, a.y); av.y = pk(a.z, a.w);
            ulonglong2 bv; bv.x = pk(b.x, b.y); bv.y = pk(b.z, b.w);
            ulonglong2 cv; cv.x = pk(c.x, c.y); cv.y = pk(c.z, c.w);
            *(ulonglong2*)&sm.z.A2[2 * k] = av;
            *(ulonglong2*)&sm.z.B2[2 * k] = bv;
            *(ulonglong2*)&sm.z.C2[2 * k] = cv;
        }
        if (tid < CBINS) sm.z.binC[tid] = __ldcg(&d_binCg[tid]);   // stashed scan
        if (tid == 0) sm.z.binC[CBINS] = N_CENT;
        __syncthreads();

        // granule mapping: slot s (0..7) -> granule s*G + bid (32 sorted particles)
        const int s = tid >> 7;
        const int t = tid & 127;
        const int q = t >> 5;          // centroid quarter, warp-uniform
        const int lane = t & 31;
        const int gran = s * G + bid;
        const bool act = (gran < NGRAN);
        const int j = gran * 32 + lane;
        float px = 0.f, py = 0.f, pwin = 0.f;
        int lo = 0x7fffffff, hi = 0;
        if (act) {
            px = __ldcg(&d_spx[j]);
            py = __ldcg(&d_spy[j]);
            pwin = __ldcg(&d_spw[j]);
            int bl = min(CBINS - 1, max(0, (int)((py - RCUT) * (float)CBINS)));
            int bh = min(CBINS, max(1, (int)((py + RCUT) * (float)CBINS) + 1));
            lo = (int)sm.z.binC[bl];
            hi = (int)sm.z.binC[bh];
        }
        int lo_w = __reduce_min_sync(0xffffffffu, lo);
        int hi_w = __reduce_max_sync(0xffffffffu, hi);
        if (lo_w > hi_w) { lo_w = 0; hi_w = 0; }
        const int s_pi = lo_w >> 1;
        const int e_pi = (hi_w + 1) >> 1;
        const int s2 = s_pi >> 1;
        const int e2 = (e_pi + 1) >> 1;
        const int ng = e2 - s2;
        const int g0 = s2 + ((ng * q) >> 2);
        const int g1 = s2 + ((ng * (q + 1)) >> 2);

        const float D = SC_CONST * (px * px + py * py);
        const u64 xx0 = pk(px, px), xx1 = pk(py, py), DD = pk(D, D);
        u64 za = 0, zb = 0;
#pragma unroll 2
        for (int g = g0; g < g1; ++g) {
            ulonglong2 a = *(const ulonglong2*)&sm.z.A2[2 * g];
            ulonglong2 b = *(const ulonglong2*)&sm.z.B2[2 * g];
            ulonglong2 c = *(const ulonglong2*)&sm.z.C2[2 * g];
            u64 u2a = fma2(a.x, xx0, fma2(b.x, xx1, add2(c.x, DD)));
            u64 u2b = fma2(a.y, xx0, fma2(b.y, xx1, add2(c.y, DD)));
            float ua, ub, uc, ud;
            upk(ua, ub, u2a);
            upk(uc, ud, u2b);
            za = add2(za, pk(fast_exp2(ua), fast_exp2(ub)));
            zb = add2(zb, pk(fast_exp2(uc), fast_exp2(ud)));
        }
        if (act) {
            float r0, r1, r2f, r3;
            upk(r0, r1, za);
            upk(r2f, r3, zb);
            sm.z.zp[s * 32 + lane][q] = (r0 + r1) + (r2f + r3);
        }
        __syncthreads();
        if (act && q == 0) {
            const int li = s * 32 + lane;
            const float Z = sm.z.zp[li][0] + sm.z.zp[li][1]
                          + sm.z.zp[li][2] + sm.z.zp[li][3];
            const float pw = pwin / Z;
            d_soa[0 * N_PART + j] = px;
            d_soa[1 * N_PART + j] = py;
            d_soa[2 * N_PART + j] = pw;
        }
    }
    gbarN(5, G);

    // ================= P6: banded gather; static tile ranges, reg accumulators ====
    {
        sm.g.pps[tid] = __ldcg(&d_ppsg[tid]);                  // stashed scan
        if (tid == 0) sm.g.pps[PBINS] = N_PART;
        __syncthreads();

        if (tid < 32) {
            int B0 = min(CBINS - 1, max(0, (int)(__ldcg(&d_scy[64 * tid]) * (float)CBINS)));
            int B1 = min(CBINS - 1, max(0, (int)(__ldcg(&d_scy[64 * tid + 63]) * (float)CBINS)));
            float yl = (float)B0 * (1.0f / CBINS) - RCUT;
            float yh = (float)(B1 + 1) * (1.0f / CBINS) + RCUT;
            int bl = min(PBINS - 1, max(0, (int)(yl * (float)PBINS)));
            int bh = min(PBINS, max(1, (int)(yh * (float)PBINS) + 1));
            unsigned jlo = sm.g.pps[bl], jhi = sm.g.pps[bh];
            sm.g.c0[tid] = jlo >> 10;
            sm.g.P[tid] = ((jhi + 1023u) >> 10) - (jlo >> 10);
        }
        __syncthreads();
        if (tid == 0) {
            unsigned run = 0;
            for (int b2 = 0; b2 < 32; ++b2) {
                unsigned t2 = sm.g.P[b2];
                sm.g.P[b2] = run;
                run += t2;
            }
            sm.g.P[32] = run;
        }
        __syncthreads();
        const unsigned ntiles = min(sm.g.P[32], 512u);
        for (unsigned t = tid; t < ntiles; t += B) {   // tile -> band map
            int lo2 = 0, hi2 = 31;
            while (lo2 < hi2) {
                int mid = (lo2 + hi2 + 1) >> 1;
                if (sm.g.P[mid] <= t) lo2 = mid; else hi2 = mid - 1;
            }
            sm.g.band[t] = (unsigned)lo2;
        }
        __syncthreads();

        const u64 SC2 = pk(SC_CONST, SC_CONST);
        const int c = tid & 63;
        const int s = tid >> 6;
        const unsigned t0 = (ntiles * (unsigned)bid) / (unsigned)G;
        const unsigned t1 = (ntiles * (unsigned)(bid + 1)) / (unsigned)G;

        u64 ax = 0, ay = 0, aw = 0;
        int curb = -1;
        float cA = 0.f, cB = 0.f, cC = 0.f;

        for (unsigned t = t0; t < t1; ++t) {
            const int b = (int)sm.g.band[t];
            if (b != curb) {
                if (curb >= 0) {   // flush accumulated band (block-uniform path)
                    float la, lb;
                    upk(la, lb, ax); sm.g.red[(s * 64 + c) * 3 + 0] = la + lb;
                    upk(la, lb, ay); sm.g.red[(s * 64 + c) * 3 + 1] = la + lb;
                    upk(la, lb, aw); sm.g.red[(s * 64 + c) * 3 + 2] = la + lb;
                    __syncthreads();
                    if (tid < 192) {
                        const int cc = tid & 63, comp = tid >> 6;
                        float sum = 0.f;
#pragma unroll
                        for (int s2 = 0; s2 < 16; ++s2)
                            sum += sm.g.red[(s2 * 64 + cc) * 3 + comp];
                        atomicAdd(&d_acc[comp * N_CENT + 64 * curb + cc], sum);
                    }
                    ax = 0; ay = 0; aw = 0;
                }
                curb = b;
                const int m = 64 * b + c;
                cA = __ldcg(&d_sA[m]); cB = __ldcg(&d_sB[m]); cC = __ldcg(&d_sC[m]);
            }
            const int ch = (int)sm.g.c0[b] + (int)(t - sm.g.P[b]);

            __syncthreads();   // tile (and red) reuse guard
            if (tid < 512) {
                const u64 px2 = __ldcg(&((const u64*)(d_soa + 0 * N_PART))[ch * 512 + tid]);
                const u64 py2 = __ldcg(&((const u64*)(d_soa + 1 * N_PART))[ch * 512 + tid]);
                sm.g.tile[tid]        = px2;
                sm.g.tile[512 + tid]  = py2;
                sm.g.tile[1024 + tid] = mul2(fma2(py2, py2, mul2(px2, px2)), SC2);
            } else {
                const int e = tid - 512;
                const u64 px2 = __ldcg(&((const u64*)(d_soa + 0 * N_PART))[ch * 512 + e]);
                const u64 py2 = __ldcg(&((const u64*)(d_soa + 1 * N_PART))[ch * 512 + e]);
                const u64 pw2 = __ldcg(&((const u64*)(d_soa + 2 * N_PART))[ch * 512 + e]);
                sm.g.tile[1536 + e] = pw2;
                sm.g.tile[2048 + e] = mul2(pw2, px2);
                sm.g.tile[2560 + e] = mul2(pw2, py2);
            }
            __syncthreads();

            const u64 A2c = pk(cA, cA), B2c = pk(cB, cB), C2c = pk(cC, cC);
#pragma unroll 4
            for (int i = 0; i < 32; i += 2) {
                const int e = s * 32 + i;   // even -> 16B aligned
                ulonglong2 vx = *(const ulonglong2*)&sm.g.tile[e];
                ulonglong2 vy = *(const ulonglong2*)&sm.g.tile[512 + e];
                ulonglong2 vD = *(const ulonglong2*)&sm.g.tile[1024 + e];
                ulonglong2 vw = *(const ulonglong2*)&sm.g.tile[1536 + e];
                ulonglong2 wx = *(const ulonglong2*)&sm.g.tile[2048 + e];
                ulonglong2 wy = *(const ulonglong2*)&sm.g.tile[2560 + e];
                {
                    u64 u2 = fma2(A2c, vx.x, fma2(B2c, vy.x, add2(C2c, vD.x)));
                    float ua, ub;
                    upk(ua, ub, u2);
                    u64 e2 = pk(fast_exp2(ua), fast_exp2(ub));
                    ax = fma2(e2, wx.x, ax);
                    ay = fma2(e2, wy.x, ay);
                    aw = fma2(e2, vw.x, aw);
                }
                {
                    u64 u2 = fma2(A2c, vx.y, fma2(B2c, vy.y, add2(C2c, vD.y)));
                    float ua, ub;
                    upk(ua, ub, u2);
                    u64 e2 = pk(fast_exp2(ua), fast_exp2(ub));
                    ax = fma2(e2, wx.y, ax);
                    ay = fma2(e2, wy.y, ay);
                    aw = fma2(e2, vw.y, aw);
                }
            }
        }
        if (curb >= 0) {   // final flush
            float la, lb;
            upk(la, lb, ax); sm.g.red[(s * 64 + c) * 3 + 0] = la + lb;
            upk(la, lb, ay); sm.g.red[(s * 64 + c) * 3 + 1] = la + lb;
            upk(la, lb, aw); sm.g.red[(s * 64 + c) * 3 + 2] = la + lb;
            __syncthreads();
            if (tid < 192) {
                const int cc = tid & 63, comp = tid >> 6;
                float sum = 0.f;
#pragma unroll
                for (int s2 = 0; s2 < 16; ++s2)
                    sum += sm.g.red[(s2 * 64 + cc) * 3 + comp];
                atomicAdd(&d_acc[comp * N_CENT + 64 * curb + cc], sum);
            }
        }
    }
    gbarN(6, G);

    // ================= P7: finalize (sorted -> rank order) + rezero ==============
    if (gid < N_CENT) {
        unsigned r = __ldcg(&d_srank[gid]);
        float ax = __ldcg(&d_acc[gid]);
        float ay = __ldcg(&d_acc[N_CENT + gid]);
        float aw = __ldcg(&d_acc[2 * N_CENT + gid]);
        out[2 * r + 0] = ax / aw;
        out[2 * r + 1] = ay / aw;
        out[2 * N_CENT + r] = aw;
    }
    if (gid < NBINS) d_hist[gid] = 0u;
    if (gid >= NBINS && gid < NBINS + PBINS) d_phist[gid - NBINS] = 0u;
}

extern "C" void kernel_launch(void* const* d_in, const int* in_sizes, int n_in,
                              void* d_out, int out_size) {
    const float* x = (const float*)d_in[0];   // [32768, 2]
    const float* w = (const float*)d_in[1];   // [32768]
    float* out = (float*)d_out;               // 6144 floats: y (4096) then v (2048)

    k_all<<<G, B>>>(x, w, out);
}